// round 9
// baseline (speedup 1.0000x reference)
#include <cuda_runtime.h>
#include <cuda_bf16.h>
#include <mma.h>
#include <cstdint>
#include <math.h>

using namespace nvcuda;

#define B_   128
#define N_   256
#define E_   2048
#define GTOT 256   // q graphs [0,128) + c graphs [128,256)

// ---------------- device scratch (static globals: no allocs) ----------------
__device__ float    g_bufA[GTOT * N_ * 128];   // 33.5 MB (s matrix)
__device__ float    g_bufB[GTOT * N_ * 32];    //  8.4 MB (final embeddings fp32)
__device__ __nv_bfloat16 g_Xhi[GTOT * N_ * 128];   // layer1 out hi (128-d)
__device__ __nv_bfloat16 g_Xlo[GTOT * N_ * 128];
__device__ __nv_bfloat16 g_Yhi[GTOT * N_ * 64];    // layer2 out hi (64-d)
__device__ __nv_bfloat16 g_Ylo[GTOT * N_ * 64];
__device__ __nv_bfloat16 g_Phi[GTOT * N_ * 32];    // final emb hi (for pair mm)
__device__ __nv_bfloat16 g_Plo[GTOT * N_ * 32];
__device__ __nv_bfloat16 g_Whi[26624];             // W1|W2|W3 bf16 hi
__device__ __nv_bfloat16 g_Wlo[26624];             // W1|W2|W3 bf16 lo
__device__ float2   g_edge[GTOT * E_];         // packed (coef, src-as-float-bits)
__device__ int      g_rowptr[GTOT * 257];
__device__ float    g_invdeg[GTOT * N_];
__device__ float    g_pool[GTOT * 32];
__device__ float    g_scoresT[B_ * 16];
__device__ unsigned g_minmax[2];
__device__ int      g_hist[16];

// monotone float<->uint mapping for atomicMin/Max over signed floats
__device__ __forceinline__ unsigned encf(float f) {
    unsigned u = __float_as_uint(f);
    return (u & 0x80000000u) ? ~u : (u | 0x80000000u);
}
__device__ __forceinline__ float decf(unsigned u) {
    return (u & 0x80000000u) ? __uint_as_float(u & 0x7fffffffu)
                             : __uint_as_float(~u);
}

// pack 4 floats -> (hi uint2, lo uint2) of bf16
__device__ __forceinline__ void split4(float4 v, uint2& hq, uint2& lq) {
    __nv_bfloat16 h0 = __float2bfloat16(v.x);
    __nv_bfloat16 h1 = __float2bfloat16(v.y);
    __nv_bfloat16 h2 = __float2bfloat16(v.z);
    __nv_bfloat16 h3 = __float2bfloat16(v.w);
    __nv_bfloat16 l0 = __float2bfloat16(v.x - __bfloat162float(h0));
    __nv_bfloat16 l1 = __float2bfloat16(v.y - __bfloat162float(h1));
    __nv_bfloat16 l2 = __float2bfloat16(v.z - __bfloat162float(h2));
    __nv_bfloat16 l3 = __float2bfloat16(v.w - __bfloat162float(h3));
    __nv_bfloat162 ph01(h0, h1), ph23(h2, h3), pl01(l0, l1), pl23(l2, l3);
    hq.x = *(unsigned*)&ph01; hq.y = *(unsigned*)&ph23;
    lq.x = *(unsigned*)&pl01; lq.y = *(unsigned*)&pl23;
}

// ---------------- weight conversion (one-shot) ----------------
__global__ void __launch_bounds__(256) k_cvtW(const float* __restrict__ W1,
                                              const float* __restrict__ W2,
                                              const float* __restrict__ W3) {
    int i = blockIdx.x * 256 + threadIdx.x;
    if (i >= 26624) return;
    float w = (i < 16384) ? W1[i] : (i < 24576 ? W2[i - 16384] : W3[i - 24576]);
    __nv_bfloat16 h = __float2bfloat16(w);
    g_Whi[i] = h;
    g_Wlo[i] = __float2bfloat16(w - __bfloat162float(h));
}

// ---------------- CSR build (per graph) + global init in block 0 ----------------
__global__ void __launch_bounds__(256) k_csr(const int* __restrict__ eq,
                                             const int* __restrict__ ec) {
    const int g = blockIdx.x;
    const int t = threadIdx.x;
    if (g == 0) {
        if (t == 0) { g_minmax[0] = 0xffffffffu; g_minmax[1] = 0u; }
        if (t < 16) g_hist[t] = 0;
    }
    const int* base = (g < B_) ? (eq + (size_t)g * 2 * E_)
                               : (ec + (size_t)(g - B_) * 2 * E_);
    const int* src = base;
    const int* dst = base + E_;

    __shared__ int   cnt[256];
    __shared__ int   scan[256];
    __shared__ int   off[256];
    __shared__ float dinv[256];

    cnt[t] = 0;
    __syncthreads();
    for (int e = t; e < E_; e += 256) atomicAdd(&cnt[dst[e]], 1);
    __syncthreads();

    float deg = (float)cnt[t] + 1.0f;
    dinv[t] = rsqrtf(deg);
    g_invdeg[g * N_ + t] = 1.0f / deg;

    int v = cnt[t];
    scan[t] = v;
    __syncthreads();
    for (int s = 1; s < 256; s <<= 1) {
        int add = (t >= s) ? scan[t - s] : 0;
        __syncthreads();
        scan[t] += add;
        __syncthreads();
    }
    int excl = scan[t] - v;
    off[t] = excl;
    g_rowptr[g * 257 + t] = excl;
    if (t == 0) g_rowptr[g * 257 + 256] = E_;
    __syncthreads();

    for (int e = t; e < E_; e += 256) {
        int d = dst[e];
        int s_ = src[e];
        int pos = atomicAdd(&off[d], 1);
        g_edge[g * E_ + pos] = make_float2(dinv[s_] * dinv[d], __int_as_float(s_));
    }
}

// ---------------- fused GCN layer: K-chunked staging + wmma + aggregate ----------------
// grid (GTOT, NSLICE); CTA = (graph, FO-slice). 512 threads.
// smem: [A chunk hi/lo | W slice hi/lo | edges | rowptr | invdeg]; H fp32 overlays [A|W].
template<int K, int KC, int FO, int FOF, int LAYER>
__global__ void __launch_bounds__(512) k_fused(
    const float* __restrict__ in0, const float* __restrict__ in1,        // L1: xq,xc
    const __nv_bfloat16* __restrict__ inHi, const __nv_bfloat16* __restrict__ inLo, // L2/3
    const __nv_bfloat16* __restrict__ Whi_, const __nv_bfloat16* __restrict__ Wlo_,
    const float* __restrict__ bias,
    __nv_bfloat16* __restrict__ outHi, __nv_bfloat16* __restrict__ outLo,
    float* __restrict__ outF)
{
    constexpr int LDA = KC + 8;
    constexpr int LDB = FO + 8;
    constexpr int ABYTES = 256 * LDA * 4;   // hi+lo bf16
    constexpr int WBYTES = K * LDB * 4;
    static_assert(256 * FO * 4 <= ABYTES + WBYTES, "H overlay too big");
    extern __shared__ __align__(16) char smc[];
    __nv_bfloat16* Ahi = (__nv_bfloat16*)smc;
    __nv_bfloat16* Alo = Ahi + 256 * LDA;
    __nv_bfloat16* Bhi = (__nv_bfloat16*)(smc + ABYTES);
    __nv_bfloat16* Blo = Bhi + K * LDB;
    float2* esm = (float2*)(smc + ABYTES + WBYTES);
    int*    rsm = (int*)(esm + E_);
    float*  dsm = (float*)(rsm + 258);

    const int g = blockIdx.x;
    const int s = blockIdx.y;
    const int t = threadIdx.x;
    const int wid = t >> 5;

    // ---- stage W slice (full K rows, FO cols) ----
    {
        constexpr int FQ = FO / 8;
        const uint4* GH = (const uint4*)Whi_;
        const uint4* GL = (const uint4*)Wlo_;
        for (int i = t; i < K * FQ; i += 512) {
            int r = i / FQ, c = i % FQ;
            int gi = r * (FOF / 8) + s * FQ + c;
            ((uint4*)(Bhi + r * LDB))[c] = GH[gi];
            ((uint4*)(Blo + r * LDB))[c] = GL[gi];
        }
    }
    for (int i = t; i < E_; i += 512) esm[i] = g_edge[(size_t)g * E_ + i];
    for (int i = t; i < 257; i += 512) rsm[i] = g_rowptr[g * 257 + i];
    for (int i = t; i < 256; i += 512) dsm[i] = g_invdeg[g * N_ + i];

    constexpr int NT = FO / 16;
    wmma::fragment<wmma::accumulator, 16, 16, 16, float> C[NT];
#pragma unroll
    for (int n = 0; n < NT; n++) wmma::fill_fragment(C[n], 0.0f);

    // ---- K-chunk loop: stage A chunk, then MMA on it ----
#pragma unroll
    for (int kc = 0; kc < K / KC; kc++) {
        if (kc) __syncthreads();   // prior MMA reads of A buffer done
        if (LAYER == 1) {
            const float* X = (g < B_) ? in0 + (size_t)g * N_ * K
                                      : in1 + (size_t)(g - B_) * N_ * K;
            const float4* X4 = (const float4*)X;
            constexpr int CQ = KC / 4;   // float4 per row-chunk
            for (int i = t; i < 256 * CQ; i += 512) {
                int r = i / CQ, c = i % CQ;
                uint2 hq, lq;
                split4(X4[r * (K / 4) + kc * CQ + c], hq, lq);
                ((uint2*)(Ahi + r * LDA))[c] = hq;
                ((uint2*)(Alo + r * LDA))[c] = lq;
            }
        } else {
            constexpr int CQ = KC / 8;   // uint4 per row-chunk
            for (int i = t; i < 256 * CQ; i += 512) {
                int r = i / CQ, c = i % CQ;
                int gi = r * (K / 8) + kc * CQ + c;
                ((uint4*)(Ahi + r * LDA))[c] = ((const uint4*)(inHi + (size_t)g * N_ * K))[gi];
                ((uint4*)(Alo + r * LDA))[c] = ((const uint4*)(inLo + (size_t)g * N_ * K))[gi];
            }
        }
        __syncthreads();

        const __nv_bfloat16* Ah = Ahi + (size_t)(wid * 16) * LDA;
        const __nv_bfloat16* Al = Alo + (size_t)(wid * 16) * LDA;
#pragma unroll
        for (int kk = 0; kk < KC; kk += 16) {
            wmma::fragment<wmma::matrix_a, 16, 16, 16, __nv_bfloat16, wmma::row_major> ah, al;
            wmma::load_matrix_sync(ah, Ah + kk, LDA);
            wmma::load_matrix_sync(al, Al + kk, LDA);
            const int krow = kc * KC + kk;
#pragma unroll
            for (int n = 0; n < NT; n++) {
                wmma::fragment<wmma::matrix_b, 16, 16, 16, __nv_bfloat16, wmma::row_major> bh, bl;
                wmma::load_matrix_sync(bh, Bhi + (size_t)krow * LDB + n * 16, LDB);
                wmma::load_matrix_sync(bl, Blo + (size_t)krow * LDB + n * 16, LDB);
                wmma::mma_sync(C[n], ah, bh, C[n]);
                wmma::mma_sync(C[n], ah, bl, C[n]);
                wmma::mma_sync(C[n], al, bh, C[n]);
            }
        }
    }
    __syncthreads();

    // ---- H fp32 overlays [A|W] ----
    float* Hs = (float*)smc;
#pragma unroll
    for (int n = 0; n < NT; n++)
        wmma::store_matrix_sync(Hs + (size_t)(wid * 16) * FO + n * 16, C[n],
                                FO, wmma::mem_row_major);
    __syncthreads();

    // ---- aggregate from smem H ----
    constexpr int QPN = FO / 4;
    constexpr int NPB = 512 / QPN;
    const int fq = t % QPN;
    const int n0 = t / QPN;
    const float4 bf = ((const float4*)(bias + s * FO))[fq];
    const float4* h4 = (const float4*)Hs;

    constexpr int RQ = FOF / 4;   // uint2 per output row
    uint2* OHI = (uint2*)outHi + (size_t)g * N_ * RQ;
    uint2* OLO = (uint2*)outLo + (size_t)g * N_ * RQ;
    float4* OF = (LAYER == 3) ? (float4*)(outF + (size_t)g * N_ * FO) : nullptr;
    uint2* PHI = (LAYER == 3) ? (uint2*)g_Phi + (size_t)g * N_ * QPN : nullptr;
    uint2* PLO = (LAYER == 3) ? (uint2*)g_Plo + (size_t)g * N_ * QPN : nullptr;

    for (int n = n0; n < N_; n += NPB) {
        const int e0 = rsm[n], e1 = rsm[n + 1];
        float4 a0 = make_float4(0.f, 0.f, 0.f, 0.f);
        float4 a1 = make_float4(0.f, 0.f, 0.f, 0.f);
        int e = e0;
        for (; e + 1 < e1; e += 2) {
            float2 ed0 = esm[e];
            float2 ed1 = esm[e + 1];
            float4 h0 = h4[__float_as_int(ed0.y) * QPN + fq];
            float4 h1 = h4[__float_as_int(ed1.y) * QPN + fq];
            a0.x += h0.x * ed0.x; a0.y += h0.y * ed0.x;
            a0.z += h0.z * ed0.x; a0.w += h0.w * ed0.x;
            a1.x += h1.x * ed1.x; a1.y += h1.y * ed1.x;
            a1.z += h1.z * ed1.x; a1.w += h1.w * ed1.x;
        }
        if (e < e1) {
            float2 ed0 = esm[e];
            float4 h0 = h4[__float_as_int(ed0.y) * QPN + fq];
            a0.x += h0.x * ed0.x; a0.y += h0.y * ed0.x;
            a0.z += h0.z * ed0.x; a0.w += h0.w * ed0.x;
        }
        const float id = dsm[n];
        float4 hs = h4[n * QPN + fq];
        float4 v;
        v.x = a0.x + a1.x + hs.x * id + bf.x;
        v.y = a0.y + a1.y + hs.y * id + bf.y;
        v.z = a0.z + a1.z + hs.z * id + bf.z;
        v.w = a0.w + a1.w + hs.w * id + bf.w;
        if (LAYER < 3) {
            v.x = fmaxf(v.x, 0.f); v.y = fmaxf(v.y, 0.f);
            v.z = fmaxf(v.z, 0.f); v.w = fmaxf(v.w, 0.f);
            uint2 hq, lq;
            split4(v, hq, lq);
            OHI[n * RQ + s * QPN + fq] = hq;
            OLO[n * RQ + s * QPN + fq] = lq;
        } else {
            OF[n * QPN + fq] = v;
            uint2 hq, lq;
            split4(v, hq, lq);
            PHI[n * QPN + fq] = hq;
            PLO[n * QPN + fq] = lq;
        }
    }
}

// ---------------- SimGNN attention pooling (f3 = 32) ----------------
__global__ void __launch_bounds__(256) k_pool(const float* __restrict__ emb,
                                              const float* __restrict__ Watt) {
    __shared__ float xs[N_ * 33];
    __shared__ float colsum[32];
    __shared__ float ctx[32];
    __shared__ float score[N_];

    const int g = blockIdx.x, t = threadIdx.x;
    const float* X = emb + (size_t)g * N_ * 32;
    for (int i = t; i < N_ * 32; i += 256)
        xs[(i >> 5) * 33 + (i & 31)] = X[i];
    __syncthreads();

    if (t < 32) {
        float s = 0.f;
        for (int n = 0; n < N_; n++) s += xs[n * 33 + t];
        colsum[t] = s;
    }
    __syncthreads();
    if (t < 32) {
        float a = 0.f;
        for (int i = 0; i < 32; i++) a += colsum[i] * Watt[t * 32 + i];
        ctx[t] = tanhf(a * (1.0f / 256.0f));
    }
    __syncthreads();
    {
        float d = 0.f;
#pragma unroll
        for (int i = 0; i < 32; i++) d += xs[t * 33 + i] * ctx[i];
        score[t] = 1.0f / (1.0f + expf(-d));
    }
    __syncthreads();
    if (t < 32) {
        float s = 0.f;
        for (int n = 0; n < N_; n++) s += xs[n * 33 + t] * score[n];
        g_pool[g * 32 + t] = s;
    }
}

// ---------------- NTN ----------------
__global__ void __launch_bounds__(512) k_ntn(const float* __restrict__ ntnW,
                                             const float* __restrict__ ntnV,
                                             const float* __restrict__ ntnb) {
    const int b = blockIdx.x;
    __shared__ float e1[32], e2[32];
    const int t = threadIdx.x;
    if (t < 32)      e1[t]      = g_pool[b * 32 + t];
    else if (t < 64) e2[t - 32] = g_pool[(B_ + b) * 32 + (t - 32)];
    __syncthreads();

    const int w = t >> 5, lane = t & 31;
    const float* Wt = ntnW + w * 1024;
    float a = 0.f;
#pragma unroll 8
    for (int j = 0; j < 32; j++) a += Wt[lane * 32 + j] * e2[j];
    float partial = e1[lane] * a
                  + e1[lane] * ntnV[w * 64 + lane]
                  + e2[lane] * ntnV[w * 64 + 32 + lane];
#pragma unroll
    for (int o = 16; o; o >>= 1)
        partial += __shfl_xor_sync(0xffffffffu, partial, o);
    if (lane == 0)
        g_scoresT[b * 16 + w] = fmaxf(partial + ntnb[w], 0.f);
}

// ---------------- pairwise dot via wmma split-bf16 + min/max from fragments ----------------
// grid (2, B_): CTA = (q row-half, batch). 256 threads = 8 warps, 16 rows each.
__global__ void __launch_bounds__(256) k_pair_mm(float* __restrict__ s) {
    constexpr int LD = 40;   // 32 + 8 pad
    __shared__ __align__(16) __nv_bfloat16 Qh[128 * LD];
    __shared__ __align__(16) __nv_bfloat16 Ql[128 * LD];
    __shared__ __align__(16) __nv_bfloat16 Ch[256 * LD];
    __shared__ __align__(16) __nv_bfloat16 Cl[256 * LD];
    __shared__ float wmn[8], wmx[8];

    const int half = blockIdx.x, b = blockIdx.y;
    const int t = threadIdx.x, wid = t >> 5, lane = t & 31;

    {
        const uint4* QH = (const uint4*)(g_Phi + ((size_t)b * N_ + half * 128) * 32);
        const uint4* QL = (const uint4*)(g_Plo + ((size_t)b * N_ + half * 128) * 32);
        for (int i = t; i < 128 * 4; i += 256) {
            int r = i / 4, c = i % 4;
            ((uint4*)(Qh + r * LD))[c] = QH[i];
            ((uint4*)(Ql + r * LD))[c] = QL[i];
        }
        const uint4* CH = (const uint4*)(g_Phi + (size_t)(B_ + b) * N_ * 32);
        const uint4* CL = (const uint4*)(g_Plo + (size_t)(B_ + b) * N_ * 32);
        for (int i = t; i < 256 * 4; i += 256) {
            int r = i / 4, c = i % 4;
            ((uint4*)(Ch + r * LD))[c] = CH[i];
            ((uint4*)(Cl + r * LD))[c] = CL[i];
        }
    }
    __syncthreads();

    wmma::fragment<wmma::matrix_a, 16, 16, 16, __nv_bfloat16, wmma::row_major> ah[2], al[2];
#pragma unroll
    for (int kt = 0; kt < 2; kt++) {
        wmma::load_matrix_sync(ah[kt], Qh + (size_t)(wid * 16) * LD + kt * 16, LD);
        wmma::load_matrix_sync(al[kt], Ql + (size_t)(wid * 16) * LD + kt * 16, LD);
    }

    float vmin = 3.402823466e38f, vmax = -3.402823466e38f;
    float* Sb = s + (size_t)b * N_ * N_ + (size_t)(half * 128 + wid * 16) * N_;

#pragma unroll
    for (int ct = 0; ct < 16; ct++) {
        wmma::fragment<wmma::accumulator, 16, 16, 16, float> acc;
        wmma::fill_fragment(acc, 0.0f);
#pragma unroll
        for (int kt = 0; kt < 2; kt++) {
            wmma::fragment<wmma::matrix_b, 16, 16, 16, __nv_bfloat16, wmma::col_major> bh, bl;
            wmma::load_matrix_sync(bh, Ch + (size_t)(ct * 16) * LD + kt * 16, LD);
            wmma::load_matrix_sync(bl, Cl + (size_t)(ct * 16) * LD + kt * 16, LD);
            wmma::mma_sync(acc, ah[kt], bh, acc);
            wmma::mma_sync(acc, ah[kt], bl, acc);
            wmma::mma_sync(acc, al[kt], bh, acc);
        }
#pragma unroll
        for (int i = 0; i < acc.num_elements; i++) {
            vmin = fminf(vmin, acc.x[i]);
            vmax = fmaxf(vmax, acc.x[i]);
        }
        wmma::store_matrix_sync(Sb + ct * 16, acc, N_, wmma::mem_row_major);
    }

#pragma unroll
    for (int o = 16; o; o >>= 1) {
        vmin = fminf(vmin, __shfl_xor_sync(0xffffffffu, vmin, o));
        vmax = fmaxf(vmax, __shfl_xor_sync(0xffffffffu, vmax, o));
    }
    if (lane == 0) { wmn[wid] = vmin; wmx[wid] = vmax; }
    __syncthreads();
    if (t == 0) {
        float m = wmn[0], M = wmx[0];
        for (int i = 1; i < 8; i++) { m = fminf(m, wmn[i]); M = fmaxf(M, wmx[i]); }
        atomicMin(&g_minmax[0], encf(m));
        atomicMax(&g_minmax[1], encf(M));
    }
}

// ---------------- histogram over 8.4M values ----------------
__global__ void __launch_bounds__(256) k_hist(const float* __restrict__ s) {
    __shared__ int hsm[16];
    const int t = threadIdx.x;
    if (t < 16) hsm[t] = 0;
    __syncthreads();

    const float lo = decf(g_minmax[0]);
    const float inv = 16.0f / (decf(g_minmax[1]) - lo);
    const int lane = t & 31;
    int cnt = 0;

    const float4* s4 = (const float4*)s;
    size_t idx0 = (size_t)blockIdx.x * 256 + t;
    for (int it = 0; it < 8; it++) {
        float4 v = s4[idx0 + (size_t)it * 262144];
        float vv[4] = {v.x, v.y, v.z, v.w};
#pragma unroll
        for (int j = 0; j < 4; j++) {
            int bi = (int)floorf((vv[j] - lo) * inv);
            bi = bi < 0 ? 0 : (bi > 15 ? 15 : bi);
#pragma unroll
            for (int b = 0; b < 16; b++) {
                unsigned m = __ballot_sync(0xffffffffu, bi == b);
                if (lane == b) cnt += __popc(m);
            }
        }
    }
    if (lane < 16) atomicAdd(&hsm[lane], cnt);
    __syncthreads();
    if (t < 16) atomicAdd(&g_hist[t], hsm[t]);
}

// ---------------- final MLP head ----------------
__global__ void k_final(const float* __restrict__ fc1W, const float* __restrict__ fc1b,
                        const float* __restrict__ fc2W, const float* __restrict__ fc2b,
                        float* __restrict__ out) {
    __shared__ float h[16];
    const int b = threadIdx.x;
    if (b < 16) h[b] = (float)g_hist[b] * (1.0f / 8388608.0f);
    __syncthreads();

    float sc[16];
#pragma unroll
    for (int t = 0; t < 16; t++) sc[t] = g_scoresT[b * 16 + t];

    float p = fc2b[0];
#pragma unroll
    for (int j = 0; j < 16; j++) {
        float a = fc1b[j];
#pragma unroll
        for (int t = 0; t < 16; t++) a += sc[t] * fc1W[j * 32 + t];
#pragma unroll
        for (int k = 0; k < 16; k++) a += h[k] * fc1W[j * 32 + 16 + k];
        p += fmaxf(a, 0.f) * fc2W[j];
    }
    out[b] = 1.0f / (1.0f + expf(-p));
}

// ---------------- launch ----------------
extern "C" void kernel_launch(void* const* d_in, const int* in_sizes, int n_in,
                              void* d_out, int out_size) {
    const float* xq   = (const float*)d_in[0];
    const float* xc   = (const float*)d_in[1];
    const int*   eq   = (const int*)d_in[2];
    const int*   ec   = (const int*)d_in[3];
    const float* W1   = (const float*)d_in[4];
    const float* b1   = (const float*)d_in[5];
    const float* W2   = (const float*)d_in[6];
    const float* b2   = (const float*)d_in[7];
    const float* W3   = (const float*)d_in[8];
    const float* b3   = (const float*)d_in[9];
    const float* Watt = (const float*)d_in[10];
    const float* ntnW = (const float*)d_in[11];
    const float* ntnV = (const float*)d_in[12];
    const float* ntnb = (const float*)d_in[13];
    const float* fc1W = (const float*)d_in[14];
    const float* fc1b = (const float*)d_in[15];
    const float* fc2W = (const float*)d_in[16];
    const float* fc2b = (const float*)d_in[17];
    float* out = (float*)d_out;

    float *bufA, *bufB;
    cudaGetSymbolAddress((void**)&bufA, g_bufA);
    cudaGetSymbolAddress((void**)&bufB, g_bufB);
    __nv_bfloat16 *Xhi, *Xlo, *Yhi, *Ylo, *Whi, *Wlo;
    cudaGetSymbolAddress((void**)&Xhi, g_Xhi);
    cudaGetSymbolAddress((void**)&Xlo, g_Xlo);
    cudaGetSymbolAddress((void**)&Yhi, g_Yhi);
    cudaGetSymbolAddress((void**)&Ylo, g_Ylo);
    cudaGetSymbolAddress((void**)&Whi, g_Whi);
    cudaGetSymbolAddress((void**)&Wlo, g_Wlo);

    // smem: A(256*40*4) + W(K*(FO+8)*4) + edges(E*8) + rowptr(258*4) + invdeg(256*4)
    constexpr int TAIL = E_ * 8 + 258 * 4 + 256 * 4;                 // 18,440
    constexpr int SMF12 = 256 * 40 * 4 + 128 * 72 * 4 + TAIL;        // 96,264
    constexpr int SMF3  = 256 * 40 * 4 + 64 * 40 * 4 + TAIL;         // 69,640

    cudaFuncSetAttribute(k_fused<128, 32, 64, 128, 1>, cudaFuncAttributeMaxDynamicSharedMemorySize, SMF12);
    cudaFuncSetAttribute(k_fused<128, 32, 64, 64,  2>, cudaFuncAttributeMaxDynamicSharedMemorySize, SMF12);
    cudaFuncSetAttribute(k_fused<64,  32, 32, 32,  3>, cudaFuncAttributeMaxDynamicSharedMemorySize, SMF3);

    k_csr<<<GTOT, 256>>>(eq, ec);
    k_cvtW<<<104, 256>>>(W1, W2, W3);

    k_fused<128, 32, 64, 128, 1><<<dim3(GTOT, 2), 512, SMF12>>>(
        xq, xc, nullptr, nullptr, Whi, Wlo, b1, Xhi, Xlo, nullptr);
    k_fused<128, 32, 64, 64, 2><<<dim3(GTOT, 1), 512, SMF12>>>(
        nullptr, nullptr, Xhi, Xlo, Whi + 16384, Wlo + 16384, b2, Yhi, Ylo, nullptr);
    k_fused<64, 32, 32, 32, 3><<<dim3(GTOT, 1), 512, SMF3>>>(
        nullptr, nullptr, Yhi, Ylo, Whi + 24576, Wlo + 24576, b3,
        nullptr, nullptr, bufB);

    k_pool<<<GTOT, 256>>>(bufB, Watt);
    k_ntn<<<B_, 512>>>(ntnW, ntnV, ntnb);

    k_pair_mm<<<dim3(2, B_), 256>>>(bufA);   // bufA = s [128,256,256]
    k_hist<<<1024, 256>>>(bufA);

    k_final<<<1, B_>>>(fc1W, fc1b, fc2W, fc2b, out);
}

// round 10
// speedup vs baseline: 1.0535x; 1.0535x over previous
#include <cuda_runtime.h>
#include <cuda_bf16.h>
#include <mma.h>
#include <cstdint>
#include <math.h>

using namespace nvcuda;

#define B_   128
#define N_   256
#define E_   2048
#define GTOT 256   // q graphs [0,128) + c graphs [128,256)

// ---------------- device scratch (static globals: no allocs) ----------------
__device__ float    g_bufA[GTOT * N_ * 128];   // 33.5 MB (s matrix)
__device__ float    g_bufB[GTOT * N_ * 32];    //  8.4 MB (final embeddings fp32)
__device__ __nv_bfloat16 g_Xhi[GTOT * N_ * 128];   // layer1 out hi (128-d)
__device__ __nv_bfloat16 g_Xlo[GTOT * N_ * 128];
__device__ __nv_bfloat16 g_Yhi[GTOT * N_ * 64];    // layer2 out hi (64-d)
__device__ __nv_bfloat16 g_Ylo[GTOT * N_ * 64];
__device__ __nv_bfloat16 g_Whi[26624];             // W1|W2|W3 bf16 hi
__device__ __nv_bfloat16 g_Wlo[26624];             // W1|W2|W3 bf16 lo
__device__ float2   g_edge[GTOT * E_];         // packed (coef, src-as-float-bits)
__device__ int      g_rowptr[GTOT * 257];
__device__ float    g_invdeg[GTOT * N_];
__device__ float    g_pool[GTOT * 32];
__device__ float    g_scoresT[B_ * 16];
__device__ unsigned g_minmax[2];
__device__ int      g_hist[16];

// monotone float<->uint mapping for atomicMin/Max over signed floats
__device__ __forceinline__ unsigned encf(float f) {
    unsigned u = __float_as_uint(f);
    return (u & 0x80000000u) ? ~u : (u | 0x80000000u);
}
__device__ __forceinline__ float decf(unsigned u) {
    return (u & 0x80000000u) ? __uint_as_float(u & 0x7fffffffu)
                             : __uint_as_float(~u);
}

// pack 4 floats -> (hi uint2, lo uint2) of bf16
__device__ __forceinline__ void split4(float4 v, uint2& hq, uint2& lq) {
    __nv_bfloat16 h0 = __float2bfloat16(v.x);
    __nv_bfloat16 h1 = __float2bfloat16(v.y);
    __nv_bfloat16 h2 = __float2bfloat16(v.z);
    __nv_bfloat16 h3 = __float2bfloat16(v.w);
    __nv_bfloat16 l0 = __float2bfloat16(v.x - __bfloat162float(h0));
    __nv_bfloat16 l1 = __float2bfloat16(v.y - __bfloat162float(h1));
    __nv_bfloat16 l2 = __float2bfloat16(v.z - __bfloat162float(h2));
    __nv_bfloat16 l3 = __float2bfloat16(v.w - __bfloat162float(h3));
    __nv_bfloat162 ph01(h0, h1), ph23(h2, h3), pl01(l0, l1), pl23(l2, l3);
    hq.x = *(unsigned*)&ph01; hq.y = *(unsigned*)&ph23;
    lq.x = *(unsigned*)&pl01; lq.y = *(unsigned*)&pl23;
}

// ---------------- weight conversion (one-shot) ----------------
__global__ void __launch_bounds__(256) k_cvtW(const float* __restrict__ W1,
                                              const float* __restrict__ W2,
                                              const float* __restrict__ W3) {
    int i = blockIdx.x * 256 + threadIdx.x;
    if (i >= 26624) return;
    float w = (i < 16384) ? W1[i] : (i < 24576 ? W2[i - 16384] : W3[i - 24576]);
    __nv_bfloat16 h = __float2bfloat16(w);
    g_Whi[i] = h;
    g_Wlo[i] = __float2bfloat16(w - __bfloat162float(h));
}

// ---------------- CSR build (per graph) + global init in block 0 ----------------
__global__ void __launch_bounds__(256) k_csr(const int* __restrict__ eq,
                                             const int* __restrict__ ec) {
    const int g = blockIdx.x;
    const int t = threadIdx.x;
    if (g == 0) {
        if (t == 0) { g_minmax[0] = 0xffffffffu; g_minmax[1] = 0u; }
        if (t < 16) g_hist[t] = 0;
    }
    const int* base = (g < B_) ? (eq + (size_t)g * 2 * E_)
                               : (ec + (size_t)(g - B_) * 2 * E_);
    const int* src = base;
    const int* dst = base + E_;

    __shared__ int   cnt[256];
    __shared__ int   scan[256];
    __shared__ int   off[256];
    __shared__ float dinv[256];

    cnt[t] = 0;
    __syncthreads();
    for (int e = t; e < E_; e += 256) atomicAdd(&cnt[dst[e]], 1);
    __syncthreads();

    float deg = (float)cnt[t] + 1.0f;
    dinv[t] = rsqrtf(deg);
    g_invdeg[g * N_ + t] = 1.0f / deg;

    int v = cnt[t];
    scan[t] = v;
    __syncthreads();
    for (int s = 1; s < 256; s <<= 1) {
        int add = (t >= s) ? scan[t - s] : 0;
        __syncthreads();
        scan[t] += add;
        __syncthreads();
    }
    int excl = scan[t] - v;
    off[t] = excl;
    g_rowptr[g * 257 + t] = excl;
    if (t == 0) g_rowptr[g * 257 + 256] = E_;
    __syncthreads();

    for (int e = t; e < E_; e += 256) {
        int d = dst[e];
        int s_ = src[e];
        int pos = atomicAdd(&off[d], 1);
        g_edge[g * E_ + pos] = make_float2(dinv[s_] * dinv[d], __int_as_float(s_));
    }
}

// ---------------- fused GCN layer: K-chunked staging + wmma + aggregate ----------------
// grid (GTOT, NSLICE); CTA = (graph, FO-slice). 512 threads, min 2 CTAs/SM.
template<int K, int KC, int FO, int FOF, int LAYER>
__global__ void __launch_bounds__(512, 2) k_fused(
    const float* __restrict__ in0, const float* __restrict__ in1,        // L1: xq,xc
    const __nv_bfloat16* __restrict__ inHi, const __nv_bfloat16* __restrict__ inLo, // L2/3
    const __nv_bfloat16* __restrict__ Whi_, const __nv_bfloat16* __restrict__ Wlo_,
    const float* __restrict__ bias,
    __nv_bfloat16* __restrict__ outHi, __nv_bfloat16* __restrict__ outLo,
    float* __restrict__ outF)
{
    constexpr int LDA = KC + 8;
    constexpr int LDB = FO + 8;
    constexpr int ABYTES = 256 * LDA * 4;   // hi+lo bf16
    constexpr int WBYTES = K * LDB * 4;
    static_assert(256 * FO * 4 <= ABYTES + WBYTES, "H overlay too big");
    extern __shared__ __align__(16) char smc[];
    __nv_bfloat16* Ahi = (__nv_bfloat16*)smc;
    __nv_bfloat16* Alo = Ahi + 256 * LDA;
    __nv_bfloat16* Bhi = (__nv_bfloat16*)(smc + ABYTES);
    __nv_bfloat16* Blo = Bhi + K * LDB;
    float2* esm = (float2*)(smc + ABYTES + WBYTES);
    int*    rsm = (int*)(esm + E_);
    float*  dsm = (float*)(rsm + 258);

    const int g = blockIdx.x;
    const int s = blockIdx.y;
    const int t = threadIdx.x;
    const int wid = t >> 5;

    // ---- stage W slice (full K rows, FO cols) ----
    {
        constexpr int FQ = FO / 8;
        const uint4* GH = (const uint4*)Whi_;
        const uint4* GL = (const uint4*)Wlo_;
        for (int i = t; i < K * FQ; i += 512) {
            int r = i / FQ, c = i % FQ;
            int gi = r * (FOF / 8) + s * FQ + c;
            ((uint4*)(Bhi + r * LDB))[c] = GH[gi];
            ((uint4*)(Blo + r * LDB))[c] = GL[gi];
        }
    }
    for (int i = t; i < E_; i += 512) esm[i] = g_edge[(size_t)g * E_ + i];
    for (int i = t; i < 257; i += 512) rsm[i] = g_rowptr[g * 257 + i];
    for (int i = t; i < 256; i += 512) dsm[i] = g_invdeg[g * N_ + i];

    constexpr int NT = FO / 16;
    wmma::fragment<wmma::accumulator, 16, 16, 16, float> C[NT];
#pragma unroll
    for (int n = 0; n < NT; n++) wmma::fill_fragment(C[n], 0.0f);

    // ---- K-chunk loop: stage A chunk, then MMA on it ----
#pragma unroll
    for (int kc = 0; kc < K / KC; kc++) {
        if (kc) __syncthreads();   // prior MMA reads of A buffer done
        if (LAYER == 1) {
            const float* X = (g < B_) ? in0 + (size_t)g * N_ * K
                                      : in1 + (size_t)(g - B_) * N_ * K;
            const float4* X4 = (const float4*)X;
            constexpr int CQ = KC / 4;   // float4 per row-chunk
            for (int i = t; i < 256 * CQ; i += 512) {
                int r = i / CQ, c = i % CQ;
                uint2 hq, lq;
                split4(X4[r * (K / 4) + kc * CQ + c], hq, lq);
                ((uint2*)(Ahi + r * LDA))[c] = hq;
                ((uint2*)(Alo + r * LDA))[c] = lq;
            }
        } else {
            constexpr int CQ = KC / 8;   // uint4 per row-chunk
            for (int i = t; i < 256 * CQ; i += 512) {
                int r = i / CQ, c = i % CQ;
                int gi = r * (K / 8) + kc * CQ + c;
                ((uint4*)(Ahi + r * LDA))[c] = ((const uint4*)(inHi + (size_t)g * N_ * K))[gi];
                ((uint4*)(Alo + r * LDA))[c] = ((const uint4*)(inLo + (size_t)g * N_ * K))[gi];
            }
        }
        __syncthreads();

        const __nv_bfloat16* Ah = Ahi + (size_t)(wid * 16) * LDA;
        const __nv_bfloat16* Al = Alo + (size_t)(wid * 16) * LDA;
#pragma unroll
        for (int kk = 0; kk < KC; kk += 16) {
            wmma::fragment<wmma::matrix_a, 16, 16, 16, __nv_bfloat16, wmma::row_major> ah, al;
            wmma::load_matrix_sync(ah, Ah + kk, LDA);
            wmma::load_matrix_sync(al, Al + kk, LDA);
            const int krow = kc * KC + kk;
#pragma unroll
            for (int n = 0; n < NT; n++) {
                wmma::fragment<wmma::matrix_b, 16, 16, 16, __nv_bfloat16, wmma::row_major> bh, bl;
                wmma::load_matrix_sync(bh, Bhi + (size_t)krow * LDB + n * 16, LDB);
                wmma::load_matrix_sync(bl, Blo + (size_t)krow * LDB + n * 16, LDB);
                wmma::mma_sync(C[n], ah, bh, C[n]);
                wmma::mma_sync(C[n], ah, bl, C[n]);
                wmma::mma_sync(C[n], al, bh, C[n]);
            }
        }
    }
    __syncthreads();

    // ---- H fp32 overlays [A|W] ----
    float* Hs = (float*)smc;
#pragma unroll
    for (int n = 0; n < NT; n++)
        wmma::store_matrix_sync(Hs + (size_t)(wid * 16) * FO + n * 16, C[n],
                                FO, wmma::mem_row_major);
    __syncthreads();

    // ---- aggregate from smem H ----
    constexpr int QPN = FO / 4;
    constexpr int NPB = 512 / QPN;
    const int fq = t % QPN;
    const int n0 = t / QPN;
    const float4 bf = ((const float4*)(bias + s * FO))[fq];
    const float4* h4 = (const float4*)Hs;

    constexpr int RQ = FOF / 4;   // uint2 per output row
    uint2* OHI = (uint2*)outHi + (size_t)g * N_ * RQ;
    uint2* OLO = (uint2*)outLo + (size_t)g * N_ * RQ;
    float4* OF = (LAYER == 3) ? (float4*)(outF + (size_t)g * N_ * FO) : nullptr;

    for (int n = n0; n < N_; n += NPB) {
        const int e0 = rsm[n], e1 = rsm[n + 1];
        float4 a0 = make_float4(0.f, 0.f, 0.f, 0.f);
        float4 a1 = make_float4(0.f, 0.f, 0.f, 0.f);
        int e = e0;
        for (; e + 1 < e1; e += 2) {
            float2 ed0 = esm[e];
            float2 ed1 = esm[e + 1];
            float4 h0 = h4[__float_as_int(ed0.y) * QPN + fq];
            float4 h1 = h4[__float_as_int(ed1.y) * QPN + fq];
            a0.x += h0.x * ed0.x; a0.y += h0.y * ed0.x;
            a0.z += h0.z * ed0.x; a0.w += h0.w * ed0.x;
            a1.x += h1.x * ed1.x; a1.y += h1.y * ed1.x;
            a1.z += h1.z * ed1.x; a1.w += h1.w * ed1.x;
        }
        if (e < e1) {
            float2 ed0 = esm[e];
            float4 h0 = h4[__float_as_int(ed0.y) * QPN + fq];
            a0.x += h0.x * ed0.x; a0.y += h0.y * ed0.x;
            a0.z += h0.z * ed0.x; a0.w += h0.w * ed0.x;
        }
        const float id = dsm[n];
        float4 hs = h4[n * QPN + fq];
        float4 v;
        v.x = a0.x + a1.x + hs.x * id + bf.x;
        v.y = a0.y + a1.y + hs.y * id + bf.y;
        v.z = a0.z + a1.z + hs.z * id + bf.z;
        v.w = a0.w + a1.w + hs.w * id + bf.w;
        if (LAYER < 3) {
            v.x = fmaxf(v.x, 0.f); v.y = fmaxf(v.y, 0.f);
            v.z = fmaxf(v.z, 0.f); v.w = fmaxf(v.w, 0.f);
            uint2 hq, lq;
            split4(v, hq, lq);
            OHI[n * RQ + s * QPN + fq] = hq;
            OLO[n * RQ + s * QPN + fq] = lq;
        } else {
            OF[n * QPN + fq] = v;
        }
    }
}

// ---------------- SimGNN attention pooling (f3 = 32) ----------------
__global__ void __launch_bounds__(256) k_pool(const float* __restrict__ emb,
                                              const float* __restrict__ Watt) {
    __shared__ float xs[N_ * 33];
    __shared__ float colsum[32];
    __shared__ float ctx[32];
    __shared__ float score[N_];

    const int g = blockIdx.x, t = threadIdx.x;
    const float* X = emb + (size_t)g * N_ * 32;
    for (int i = t; i < N_ * 32; i += 256)
        xs[(i >> 5) * 33 + (i & 31)] = X[i];
    __syncthreads();

    if (t < 32) {
        float s = 0.f;
        for (int n = 0; n < N_; n++) s += xs[n * 33 + t];
        colsum[t] = s;
    }
    __syncthreads();
    if (t < 32) {
        float a = 0.f;
        for (int i = 0; i < 32; i++) a += colsum[i] * Watt[t * 32 + i];
        ctx[t] = tanhf(a * (1.0f / 256.0f));
    }
    __syncthreads();
    {
        float d = 0.f;
#pragma unroll
        for (int i = 0; i < 32; i++) d += xs[t * 33 + i] * ctx[i];
        score[t] = 1.0f / (1.0f + expf(-d));
    }
    __syncthreads();
    if (t < 32) {
        float s = 0.f;
        for (int n = 0; n < N_; n++) s += xs[n * 33 + t] * score[n];
        g_pool[g * 32 + t] = s;
    }
}

// ---------------- NTN ----------------
__global__ void __launch_bounds__(512) k_ntn(const float* __restrict__ ntnW,
                                             const float* __restrict__ ntnV,
                                             const float* __restrict__ ntnb) {
    const int b = blockIdx.x;
    __shared__ float e1[32], e2[32];
    const int t = threadIdx.x;
    if (t < 32)      e1[t]      = g_pool[b * 32 + t];
    else if (t < 64) e2[t - 32] = g_pool[(B_ + b) * 32 + (t - 32)];
    __syncthreads();

    const int w = t >> 5, lane = t & 31;
    const float* Wt = ntnW + w * 1024;
    float a = 0.f;
#pragma unroll 8
    for (int j = 0; j < 32; j++) a += Wt[lane * 32 + j] * e2[j];
    float partial = e1[lane] * a
                  + e1[lane] * ntnV[w * 64 + lane]
                  + e2[lane] * ntnV[w * 64 + 32 + lane];
#pragma unroll
    for (int o = 16; o; o >>= 1)
        partial += __shfl_xor_sync(0xffffffffu, partial, o);
    if (lane == 0)
        g_scoresT[b * 16 + w] = fmaxf(partial + ntnb[w], 0.f);
}

// ---------------- pairwise dot s[b,n,m] = q_n . c_m, plus global min/max ----------------
__global__ void __launch_bounds__(256) k_pair(const float* __restrict__ emb,
                                              float* __restrict__ s) {
    __shared__ float qs[64 * 32];
    __shared__ float cs[256 * 33];
    __shared__ float wmn[8], wmx[8];

    const int b = blockIdx.y, nt = blockIdx.x;
    const int t = threadIdx.x;
    const float* Q = emb + (size_t)b * N_ * 32 + (size_t)nt * 64 * 32;
    const float* C = emb + (size_t)(B_ + b) * N_ * 32;
    for (int i = t; i < 64 * 32; i += 256) qs[i] = Q[i];
    for (int i = t; i < 256 * 32; i += 256)
        cs[(i >> 5) * 33 + (i & 31)] = C[i];
    __syncthreads();

    float cr[32];
#pragma unroll
    for (int k = 0; k < 32; k++) cr[k] = cs[t * 33 + k];

    float vmin = 3.402823466e38f, vmax = -3.402823466e38f;
    float* Sb = s + (size_t)b * N_ * N_ + (size_t)nt * 64 * N_;
    for (int n = 0; n < 64; n += 4) {
        float a0 = 0.f, a1 = 0.f, a2 = 0.f, a3 = 0.f;
#pragma unroll
        for (int k = 0; k < 32; k++) {
            float cv = cr[k];
            a0 += qs[(n + 0) * 32 + k] * cv;
            a1 += qs[(n + 1) * 32 + k] * cv;
            a2 += qs[(n + 2) * 32 + k] * cv;
            a3 += qs[(n + 3) * 32 + k] * cv;
        }
        Sb[(n + 0) * N_ + t] = a0;
        Sb[(n + 1) * N_ + t] = a1;
        Sb[(n + 2) * N_ + t] = a2;
        Sb[(n + 3) * N_ + t] = a3;
        vmin = fminf(fminf(vmin, a0), fminf(fminf(a1, a2), a3));
        vmax = fmaxf(fmaxf(vmax, a0), fmaxf(fmaxf(a1, a2), a3));
    }
#pragma unroll
    for (int o = 16; o; o >>= 1) {
        vmin = fminf(vmin, __shfl_xor_sync(0xffffffffu, vmin, o));
        vmax = fmaxf(vmax, __shfl_xor_sync(0xffffffffu, vmax, o));
    }
    if ((t & 31) == 0) { wmn[t >> 5] = vmin; wmx[t >> 5] = vmax; }
    __syncthreads();
    if (t == 0) {
        float m = wmn[0], M = wmx[0];
        for (int i = 1; i < 8; i++) { m = fminf(m, wmn[i]); M = fmaxf(M, wmx[i]); }
        atomicMin(&g_minmax[0], encf(m));
        atomicMax(&g_minmax[1], encf(M));
    }
}

// ---------------- histogram over 8.4M values ----------------
__global__ void __launch_bounds__(256) k_hist(const float* __restrict__ s) {
    __shared__ int hsm[16];
    const int t = threadIdx.x;
    if (t < 16) hsm[t] = 0;
    __syncthreads();

    const float lo = decf(g_minmax[0]);
    const float inv = 16.0f / (decf(g_minmax[1]) - lo);
    const int lane = t & 31;
    int cnt = 0;

    const float4* s4 = (const float4*)s;
    size_t idx0 = (size_t)blockIdx.x * 256 + t;
    for (int it = 0; it < 8; it++) {
        float4 v = s4[idx0 + (size_t)it * 262144];
        float vv[4] = {v.x, v.y, v.z, v.w};
#pragma unroll
        for (int j = 0; j < 4; j++) {
            int bi = (int)floorf((vv[j] - lo) * inv);
            bi = bi < 0 ? 0 : (bi > 15 ? 15 : bi);
#pragma unroll
            for (int b = 0; b < 16; b++) {
                unsigned m = __ballot_sync(0xffffffffu, bi == b);
                if (lane == b) cnt += __popc(m);
            }
        }
    }
    if (lane < 16) atomicAdd(&hsm[lane], cnt);
    __syncthreads();
    if (t < 16) atomicAdd(&g_hist[t], hsm[t]);
}

// ---------------- final MLP head ----------------
__global__ void k_final(const float* __restrict__ fc1W, const float* __restrict__ fc1b,
                        const float* __restrict__ fc2W, const float* __restrict__ fc2b,
                        float* __restrict__ out) {
    __shared__ float h[16];
    const int b = threadIdx.x;
    if (b < 16) h[b] = (float)g_hist[b] * (1.0f / 8388608.0f);
    __syncthreads();

    float sc[16];
#pragma unroll
    for (int t = 0; t < 16; t++) sc[t] = g_scoresT[b * 16 + t];

    float p = fc2b[0];
#pragma unroll
    for (int j = 0; j < 16; j++) {
        float a = fc1b[j];
#pragma unroll
        for (int t = 0; t < 16; t++) a += sc[t] * fc1W[j * 32 + t];
#pragma unroll
        for (int k = 0; k < 16; k++) a += h[k] * fc1W[j * 32 + 16 + k];
        p += fmaxf(a, 0.f) * fc2W[j];
    }
    out[b] = 1.0f / (1.0f + expf(-p));
}

// ---------------- launch ----------------
extern "C" void kernel_launch(void* const* d_in, const int* in_sizes, int n_in,
                              void* d_out, int out_size) {
    const float* xq   = (const float*)d_in[0];
    const float* xc   = (const float*)d_in[1];
    const int*   eq   = (const int*)d_in[2];
    const int*   ec   = (const int*)d_in[3];
    const float* W1   = (const float*)d_in[4];
    const float* b1   = (const float*)d_in[5];
    const float* W2   = (const float*)d_in[6];
    const float* b2   = (const float*)d_in[7];
    const float* W3   = (const float*)d_in[8];
    const float* b3   = (const float*)d_in[9];
    const float* Watt = (const float*)d_in[10];
    const float* ntnW = (const float*)d_in[11];
    const float* ntnV = (const float*)d_in[12];
    const float* ntnb = (const float*)d_in[13];
    const float* fc1W = (const float*)d_in[14];
    const float* fc1b = (const float*)d_in[15];
    const float* fc2W = (const float*)d_in[16];
    const float* fc2b = (const float*)d_in[17];
    float* out = (float*)d_out;

    float *bufA, *bufB;
    cudaGetSymbolAddress((void**)&bufA, g_bufA);
    cudaGetSymbolAddress((void**)&bufB, g_bufB);
    __nv_bfloat16 *Xhi, *Xlo, *Yhi, *Ylo, *Whi, *Wlo;
    cudaGetSymbolAddress((void**)&Xhi, g_Xhi);
    cudaGetSymbolAddress((void**)&Xlo, g_Xlo);
    cudaGetSymbolAddress((void**)&Yhi, g_Yhi);
    cudaGetSymbolAddress((void**)&Ylo, g_Ylo);
    cudaGetSymbolAddress((void**)&Whi, g_Whi);
    cudaGetSymbolAddress((void**)&Wlo, g_Wlo);

    // smem: A(256*40*4) + W(K*(FO+8)*4) + edges(E*8) + rowptr(258*4) + invdeg(256*4)
    constexpr int TAIL = E_ * 8 + 258 * 4 + 256 * 4;                 // 18,440
    constexpr int SMF12 = 256 * 40 * 4 + 128 * 72 * 4 + TAIL;        // 96,264
    constexpr int SMF3  = 256 * 40 * 4 + 64 * 40 * 4 + TAIL;         // 69,640

    cudaFuncSetAttribute(k_fused<128, 32, 64, 128, 1>, cudaFuncAttributeMaxDynamicSharedMemorySize, SMF12);
    cudaFuncSetAttribute(k_fused<128, 32, 64, 64,  2>, cudaFuncAttributeMaxDynamicSharedMemorySize, SMF12);
    cudaFuncSetAttribute(k_fused<64,  32, 32, 32,  3>, cudaFuncAttributeMaxDynamicSharedMemorySize, SMF3);

    k_csr<<<GTOT, 256>>>(eq, ec);
    k_cvtW<<<104, 256>>>(W1, W2, W3);

    k_fused<128, 32, 64, 128, 1><<<dim3(GTOT, 2), 512, SMF12>>>(
        xq, xc, nullptr, nullptr, Whi, Wlo, b1, Xhi, Xlo, nullptr);
    k_fused<128, 32, 64, 64, 2><<<dim3(GTOT, 1), 512, SMF12>>>(
        nullptr, nullptr, Xhi, Xlo, Whi + 16384, Wlo + 16384, b2, Yhi, Ylo, nullptr);
    k_fused<64, 32, 32, 32, 3><<<dim3(GTOT, 1), 512, SMF3>>>(
        nullptr, nullptr, Yhi, Ylo, Whi + 24576, Wlo + 24576, b3,
        nullptr, nullptr, bufB);

    k_pool<<<GTOT, 256>>>(bufB, Watt);
    k_ntn<<<B_, 512>>>(ntnW, ntnV, ntnb);

    k_pair<<<dim3(4, B_), 256>>>(bufB, bufA);   // bufA = s [128,256,256]
    k_hist<<<1024, 256>>>(bufA);

    k_final<<<1, B_>>>(fc1W, fc1b, fc2W, fc2b, out);
}

// round 11
// speedup vs baseline: 1.3006x; 1.2346x over previous
#include <cuda_runtime.h>
#include <cuda_bf16.h>
#include <mma.h>
#include <cstdint>
#include <math.h>

using namespace nvcuda;

#define B_   128
#define N_   256
#define E_   2048
#define GTOT 256   // q graphs [0,128) + c graphs [128,256)

// ---------------- device scratch (static globals: no allocs) ----------------
__device__ float    g_bufB[GTOT * N_ * 32];    //  8.4 MB (final embeddings fp32)
__device__ __nv_bfloat16 g_Xhi[GTOT * N_ * 128];   // layer1 out hi (128-d)
__device__ __nv_bfloat16 g_Xlo[GTOT * N_ * 128];
__device__ __nv_bfloat16 g_Yhi[GTOT * N_ * 64];    // layer2 out hi (64-d)
__device__ __nv_bfloat16 g_Ylo[GTOT * N_ * 64];
__device__ __nv_bfloat16 g_Phi[GTOT * N_ * 32];    // final emb hi (for pair mm)
__device__ __nv_bfloat16 g_Plo[GTOT * N_ * 32];
__device__ __nv_bfloat16 g_Whi[26624];             // W1|W2|W3 bf16 hi
__device__ __nv_bfloat16 g_Wlo[26624];             // W1|W2|W3 bf16 lo
__device__ float2   g_edge[GTOT * E_];         // packed (coef, src-as-float-bits)
__device__ int      g_rowptr[GTOT * 257];
__device__ float    g_invdeg[GTOT * N_];
__device__ float    g_pool[GTOT * 32];
__device__ float    g_scoresT[B_ * 16];
__device__ unsigned g_minmax[2];
__device__ int      g_hist[16];

// monotone float<->uint mapping for atomicMin/Max over signed floats
__device__ __forceinline__ unsigned encf(float f) {
    unsigned u = __float_as_uint(f);
    return (u & 0x80000000u) ? ~u : (u | 0x80000000u);
}
__device__ __forceinline__ float decf(unsigned u) {
    return (u & 0x80000000u) ? __uint_as_float(u & 0x7fffffffu)
                             : __uint_as_float(~u);
}

// pack 4 floats -> (hi uint2, lo uint2) of bf16
__device__ __forceinline__ void split4(float4 v, uint2& hq, uint2& lq) {
    __nv_bfloat16 h0 = __float2bfloat16(v.x);
    __nv_bfloat16 h1 = __float2bfloat16(v.y);
    __nv_bfloat16 h2 = __float2bfloat16(v.z);
    __nv_bfloat16 h3 = __float2bfloat16(v.w);
    __nv_bfloat16 l0 = __float2bfloat16(v.x - __bfloat162float(h0));
    __nv_bfloat16 l1 = __float2bfloat16(v.y - __bfloat162float(h1));
    __nv_bfloat16 l2 = __float2bfloat16(v.z - __bfloat162float(h2));
    __nv_bfloat16 l3 = __float2bfloat16(v.w - __bfloat162float(h3));
    __nv_bfloat162 ph01(h0, h1), ph23(h2, h3), pl01(l0, l1), pl23(l2, l3);
    hq.x = *(unsigned*)&ph01; hq.y = *(unsigned*)&ph23;
    lq.x = *(unsigned*)&pl01; lq.y = *(unsigned*)&pl23;
}

// ---------------- weight conversion (one-shot) ----------------
__global__ void __launch_bounds__(256) k_cvtW(const float* __restrict__ W1,
                                              const float* __restrict__ W2,
                                              const float* __restrict__ W3) {
    int i = blockIdx.x * 256 + threadIdx.x;
    if (i >= 26624) return;
    float w = (i < 16384) ? W1[i] : (i < 24576 ? W2[i - 16384] : W3[i - 24576]);
    __nv_bfloat16 h = __float2bfloat16(w);
    g_Whi[i] = h;
    g_Wlo[i] = __float2bfloat16(w - __bfloat162float(h));
}

// ---------------- CSR build (per graph) + global init in block 0 ----------------
__global__ void __launch_bounds__(256) k_csr(const int* __restrict__ eq,
                                             const int* __restrict__ ec) {
    const int g = blockIdx.x;
    const int t = threadIdx.x;
    if (g == 0) {
        if (t == 0) { g_minmax[0] = 0xffffffffu; g_minmax[1] = 0u; }
        if (t < 16) g_hist[t] = 0;
    }
    const int* base = (g < B_) ? (eq + (size_t)g * 2 * E_)
                               : (ec + (size_t)(g - B_) * 2 * E_);
    const int* src = base;
    const int* dst = base + E_;

    __shared__ int   cnt[256];
    __shared__ int   scan[256];
    __shared__ int   off[256];
    __shared__ float dinv[256];

    cnt[t] = 0;
    __syncthreads();
    for (int e = t; e < E_; e += 256) atomicAdd(&cnt[dst[e]], 1);
    __syncthreads();

    float deg = (float)cnt[t] + 1.0f;
    dinv[t] = rsqrtf(deg);
    g_invdeg[g * N_ + t] = 1.0f / deg;

    int v = cnt[t];
    scan[t] = v;
    __syncthreads();
    for (int s = 1; s < 256; s <<= 1) {
        int add = (t >= s) ? scan[t - s] : 0;
        __syncthreads();
        scan[t] += add;
        __syncthreads();
    }
    int excl = scan[t] - v;
    off[t] = excl;
    g_rowptr[g * 257 + t] = excl;
    if (t == 0) g_rowptr[g * 257 + 256] = E_;
    __syncthreads();

    for (int e = t; e < E_; e += 256) {
        int d = dst[e];
        int s_ = src[e];
        int pos = atomicAdd(&off[d], 1);
        g_edge[g * E_ + pos] = make_float2(dinv[s_] * dinv[d], __int_as_float(s_));
    }
}

// ---------------- fused GCN layer (R8 structure): stage -> wmma -> H smem -> agg ----------------
template<int K, int FO, int LAYER>
__global__ void __launch_bounds__(512) k_fused(
    const float* __restrict__ in0, const float* __restrict__ in1,        // L1: xq,xc
    const __nv_bfloat16* __restrict__ inHi, const __nv_bfloat16* __restrict__ inLo, // L2/3
    const __nv_bfloat16* __restrict__ Whi_, const __nv_bfloat16* __restrict__ Wlo_,
    const float* __restrict__ bias,
    __nv_bfloat16* __restrict__ outHi, __nv_bfloat16* __restrict__ outLo, // L1/2
    float* __restrict__ outF)                                             // L3
{
    constexpr int LDA = K + 8;
    constexpr int LDB = FO + 8;
    extern __shared__ __align__(16) char smc[];
    __nv_bfloat16* Ahi = (__nv_bfloat16*)smc;          // 256*LDA
    __nv_bfloat16* Alo = Ahi + 256 * LDA;
    __nv_bfloat16* Bhi = Alo + 256 * LDA;              // K*LDB
    __nv_bfloat16* Blo = Bhi + K * LDB;
    float2* esm = (float2*)(Blo + K * LDB);            // E_
    int*    rsm = (int*)(esm + E_);                    // 258 (257 used)
    float*  dsm = (float*)(rsm + 258);                 // 256

    const int g = blockIdx.x;
    const int t = threadIdx.x;
    const int wid = t >> 5;

    // ---- stage A ----
    if (LAYER == 1) {
        const float* X = (g < B_) ? in0 + (size_t)g * N_ * K
                                  : in1 + (size_t)(g - B_) * N_ * K;
        const float4* X4 = (const float4*)X;
        constexpr int KQ = K / 4;
        for (int i = t; i < N_ * KQ; i += 512) {
            int r = i / KQ, c = i % KQ;
            uint2 hq, lq;
            split4(X4[i], hq, lq);
            ((uint2*)(Ahi + r * LDA))[c] = hq;
            ((uint2*)(Alo + r * LDA))[c] = lq;
        }
    } else {
        constexpr int KQ = K / 8;
        const uint4* GH = (const uint4*)(inHi + (size_t)g * N_ * K);
        const uint4* GL = (const uint4*)(inLo + (size_t)g * N_ * K);
        for (int i = t; i < N_ * KQ; i += 512) {
            int r = i / KQ, c = i % KQ;
            ((uint4*)(Ahi + r * LDA))[c] = GH[i];
            ((uint4*)(Alo + r * LDA))[c] = GL[i];
        }
    }
    // ---- stage W ----
    {
        constexpr int FQ = FO / 8;
        const uint4* GH = (const uint4*)Whi_;
        const uint4* GL = (const uint4*)Wlo_;
        for (int i = t; i < K * FQ; i += 512) {
            int r = i / FQ, c = i % FQ;
            ((uint4*)(Bhi + r * LDB))[c] = GH[i];
            ((uint4*)(Blo + r * LDB))[c] = GL[i];
        }
    }
    for (int i = t; i < E_; i += 512) esm[i] = g_edge[(size_t)g * E_ + i];
    for (int i = t; i < 257; i += 512) rsm[i] = g_rowptr[g * 257 + i];
    for (int i = t; i < 256; i += 512) dsm[i] = g_invdeg[g * N_ + i];
    __syncthreads();

    // ---- wmma GEMM: 16 warps x 16 rows ----
    constexpr int NT = FO / 16;
    wmma::fragment<wmma::accumulator, 16, 16, 16, float> C[NT];
#pragma unroll
    for (int n = 0; n < NT; n++) wmma::fill_fragment(C[n], 0.0f);

    const __nv_bfloat16* Ah = Ahi + (size_t)(wid * 16) * LDA;
    const __nv_bfloat16* Al = Alo + (size_t)(wid * 16) * LDA;

#pragma unroll
    for (int k0 = 0; k0 < K; k0 += 16) {
        wmma::fragment<wmma::matrix_a, 16, 16, 16, __nv_bfloat16, wmma::row_major> ah, al;
        wmma::load_matrix_sync(ah, Ah + k0, LDA);
        wmma::load_matrix_sync(al, Al + k0, LDA);
#pragma unroll
        for (int n = 0; n < NT; n++) {
            wmma::fragment<wmma::matrix_b, 16, 16, 16, __nv_bfloat16, wmma::row_major> bh, bl;
            wmma::load_matrix_sync(bh, Bhi + (size_t)k0 * LDB + n * 16, LDB);
            wmma::load_matrix_sync(bl, Blo + (size_t)k0 * LDB + n * 16, LDB);
            wmma::mma_sync(C[n], ah, bh, C[n]);
            wmma::mma_sync(C[n], ah, bl, C[n]);
            wmma::mma_sync(C[n], al, bh, C[n]);
        }
    }
    __syncthreads();

    // ---- H fp32 into smem (reusing A region) ----
    float* Hs = (float*)smc;
#pragma unroll
    for (int n = 0; n < NT; n++)
        wmma::store_matrix_sync(Hs + (size_t)(wid * 16) * FO + n * 16, C[n],
                                FO, wmma::mem_row_major);
    __syncthreads();

    // ---- aggregate from smem H ----
    constexpr int QPN = FO / 4;
    constexpr int NPB = 512 / QPN;
    const int fq = t % QPN;
    const int n0 = t / QPN;
    const float4 bf = ((const float4*)bias)[fq];
    const float4* h4 = (const float4*)Hs;

    uint2* OHI = (uint2*)outHi + (size_t)g * N_ * QPN;
    uint2* OLO = (uint2*)outLo + (size_t)g * N_ * QPN;
    float4* OF = (LAYER == 3) ? (float4*)(outF + (size_t)g * N_ * FO) : nullptr;
    uint2* PHI = (LAYER == 3) ? (uint2*)g_Phi + (size_t)g * N_ * QPN : nullptr;
    uint2* PLO = (LAYER == 3) ? (uint2*)g_Plo + (size_t)g * N_ * QPN : nullptr;

    for (int n = n0; n < N_; n += NPB) {
        const int e0 = rsm[n], e1 = rsm[n + 1];
        float4 a0 = make_float4(0.f, 0.f, 0.f, 0.f);
        float4 a1 = make_float4(0.f, 0.f, 0.f, 0.f);
        int e = e0;
        for (; e + 1 < e1; e += 2) {
            float2 ed0 = esm[e];
            float2 ed1 = esm[e + 1];
            float4 h0 = h4[__float_as_int(ed0.y) * QPN + fq];
            float4 h1 = h4[__float_as_int(ed1.y) * QPN + fq];
            a0.x += h0.x * ed0.x; a0.y += h0.y * ed0.x;
            a0.z += h0.z * ed0.x; a0.w += h0.w * ed0.x;
            a1.x += h1.x * ed1.x; a1.y += h1.y * ed1.x;
            a1.z += h1.z * ed1.x; a1.w += h1.w * ed1.x;
        }
        if (e < e1) {
            float2 ed0 = esm[e];
            float4 h0 = h4[__float_as_int(ed0.y) * QPN + fq];
            a0.x += h0.x * ed0.x; a0.y += h0.y * ed0.x;
            a0.z += h0.z * ed0.x; a0.w += h0.w * ed0.x;
        }
        const float id = dsm[n];
        float4 hs = h4[n * QPN + fq];
        float4 v;
        v.x = a0.x + a1.x + hs.x * id + bf.x;
        v.y = a0.y + a1.y + hs.y * id + bf.y;
        v.z = a0.z + a1.z + hs.z * id + bf.z;
        v.w = a0.w + a1.w + hs.w * id + bf.w;
        if (LAYER < 3) {
            v.x = fmaxf(v.x, 0.f); v.y = fmaxf(v.y, 0.f);
            v.z = fmaxf(v.z, 0.f); v.w = fmaxf(v.w, 0.f);
            uint2 hq, lq;
            split4(v, hq, lq);
            OHI[n * QPN + fq] = hq;
            OLO[n * QPN + fq] = lq;
        } else {
            OF[n * QPN + fq] = v;
            uint2 hq, lq;
            split4(v, hq, lq);
            PHI[n * QPN + fq] = hq;
            PLO[n * QPN + fq] = lq;
        }
    }
}

// ---------------- SimGNN attention pooling (f3 = 32) ----------------
__global__ void __launch_bounds__(256) k_pool(const float* __restrict__ emb,
                                              const float* __restrict__ Watt) {
    __shared__ float xs[N_ * 33];
    __shared__ float colsum[32];
    __shared__ float ctx[32];
    __shared__ float score[N_];

    const int g = blockIdx.x, t = threadIdx.x;
    const float* X = emb + (size_t)g * N_ * 32;
    for (int i = t; i < N_ * 32; i += 256)
        xs[(i >> 5) * 33 + (i & 31)] = X[i];
    __syncthreads();

    if (t < 32) {
        float s = 0.f;
        for (int n = 0; n < N_; n++) s += xs[n * 33 + t];
        colsum[t] = s;
    }
    __syncthreads();
    if (t < 32) {
        float a = 0.f;
        for (int i = 0; i < 32; i++) a += colsum[i] * Watt[t * 32 + i];
        ctx[t] = tanhf(a * (1.0f / 256.0f));
    }
    __syncthreads();
    {
        float d = 0.f;
#pragma unroll
        for (int i = 0; i < 32; i++) d += xs[t * 33 + i] * ctx[i];
        score[t] = 1.0f / (1.0f + expf(-d));
    }
    __syncthreads();
    if (t < 32) {
        float s = 0.f;
        for (int n = 0; n < N_; n++) s += xs[n * 33 + t] * score[n];
        g_pool[g * 32 + t] = s;
    }
}

// ---------------- NTN ----------------
__global__ void __launch_bounds__(512) k_ntn(const float* __restrict__ ntnW,
                                             const float* __restrict__ ntnV,
                                             const float* __restrict__ ntnb) {
    const int b = blockIdx.x;
    __shared__ float e1[32], e2[32];
    const int t = threadIdx.x;
    if (t < 32)      e1[t]      = g_pool[b * 32 + t];
    else if (t < 64) e2[t - 32] = g_pool[(B_ + b) * 32 + (t - 32)];
    __syncthreads();

    const int w = t >> 5, lane = t & 31;
    const float* Wt = ntnW + w * 1024;
    float a = 0.f;
#pragma unroll 8
    for (int j = 0; j < 32; j++) a += Wt[lane * 32 + j] * e2[j];
    float partial = e1[lane] * a
                  + e1[lane] * ntnV[w * 64 + lane]
                  + e2[lane] * ntnV[w * 64 + 32 + lane];
#pragma unroll
    for (int o = 16; o; o >>= 1)
        partial += __shfl_xor_sync(0xffffffffu, partial, o);
    if (lane == 0)
        g_scoresT[b * 16 + w] = fmaxf(partial + ntnb[w], 0.f);
}

// ============ pair matrix: shared staging + split-bf16 wmma tile compute ============
// Each CTA: (half, b). 8 warps x 16 q-rows; loops 16 col tiles. No s stored to DRAM.
template<typename F>
__device__ __forceinline__ void pair_tiles(int half, int b, int t, F&& consume) {
    constexpr int LD = 40;
    __shared__ __align__(16) __nv_bfloat16 Qh[128 * LD];
    __shared__ __align__(16) __nv_bfloat16 Ql[128 * LD];
    __shared__ __align__(16) __nv_bfloat16 Ch[256 * LD];
    __shared__ __align__(16) __nv_bfloat16 Cl[256 * LD];

    const int wid = t >> 5;

    {
        const uint4* QH = (const uint4*)(g_Phi + ((size_t)b * N_ + half * 128) * 32);
        const uint4* QL = (const uint4*)(g_Plo + ((size_t)b * N_ + half * 128) * 32);
        for (int i = t; i < 128 * 4; i += 256) {
            int r = i / 4, c = i % 4;
            ((uint4*)(Qh + r * LD))[c] = QH[i];
            ((uint4*)(Ql + r * LD))[c] = QL[i];
        }
        const uint4* CH = (const uint4*)(g_Phi + (size_t)(B_ + b) * N_ * 32);
        const uint4* CL = (const uint4*)(g_Plo + (size_t)(B_ + b) * N_ * 32);
        for (int i = t; i < 256 * 4; i += 256) {
            int r = i / 4, c = i % 4;
            ((uint4*)(Ch + r * LD))[c] = CH[i];
            ((uint4*)(Cl + r * LD))[c] = CL[i];
        }
    }
    __syncthreads();

    wmma::fragment<wmma::matrix_a, 16, 16, 16, __nv_bfloat16, wmma::row_major> ah[2], al[2];
#pragma unroll
    for (int kt = 0; kt < 2; kt++) {
        wmma::load_matrix_sync(ah[kt], Qh + (size_t)(wid * 16) * LD + kt * 16, LD);
        wmma::load_matrix_sync(al[kt], Ql + (size_t)(wid * 16) * LD + kt * 16, LD);
    }

#pragma unroll
    for (int ct = 0; ct < 16; ct++) {
        wmma::fragment<wmma::accumulator, 16, 16, 16, float> acc;
        wmma::fill_fragment(acc, 0.0f);
#pragma unroll
        for (int kt = 0; kt < 2; kt++) {
            wmma::fragment<wmma::matrix_b, 16, 16, 16, __nv_bfloat16, wmma::col_major> bh, bl;
            wmma::load_matrix_sync(bh, Ch + (size_t)(ct * 16) * LD + kt * 16, LD);
            wmma::load_matrix_sync(bl, Cl + (size_t)(ct * 16) * LD + kt * 16, LD);
            wmma::mma_sync(acc, ah[kt], bh, acc);
            wmma::mma_sync(acc, ah[kt], bl, acc);
            wmma::mma_sync(acc, al[kt], bh, acc);
        }
        consume(acc);
    }
}

// ---- pass 1: global min/max only ----
__global__ void __launch_bounds__(256) k_pair_minmax() {
    __shared__ float wmn[8], wmx[8];
    const int half = blockIdx.x, b = blockIdx.y;
    const int t = threadIdx.x, wid = t >> 5, lane = t & 31;

    float vmin = 3.402823466e38f, vmax = -3.402823466e38f;
    pair_tiles(half, b, t,
        [&](wmma::fragment<wmma::accumulator, 16, 16, 16, float>& acc) {
#pragma unroll
            for (int i = 0; i < acc.num_elements; i++) {
                vmin = fminf(vmin, acc.x[i]);
                vmax = fmaxf(vmax, acc.x[i]);
            }
        });

#pragma unroll
    for (int o = 16; o; o >>= 1) {
        vmin = fminf(vmin, __shfl_xor_sync(0xffffffffu, vmin, o));
        vmax = fmaxf(vmax, __shfl_xor_sync(0xffffffffu, vmax, o));
    }
    if (lane == 0) { wmn[wid] = vmin; wmx[wid] = vmax; }
    __syncthreads();
    if (t == 0) {
        float m = wmn[0], M = wmx[0];
        for (int i = 1; i < 8; i++) { m = fminf(m, wmn[i]); M = fmaxf(M, wmx[i]); }
        atomicMin(&g_minmax[0], encf(m));
        atomicMax(&g_minmax[1], encf(M));
    }
}

// ---- pass 2: recompute identical tiles, histogram directly ----
__global__ void __launch_bounds__(256) k_pair_hist() {
    __shared__ int hsm[8][16];
    const int half = blockIdx.x, b = blockIdx.y;
    const int t = threadIdx.x, wid = t >> 5;

    if ((t & 31) < 16) hsm[wid][t & 15] = 0;
    __syncthreads();

    const float lo = decf(g_minmax[0]);
    const float inv = 16.0f / (decf(g_minmax[1]) - lo);
    int* myh = hsm[wid];

    pair_tiles(half, b, t,
        [&](wmma::fragment<wmma::accumulator, 16, 16, 16, float>& acc) {
#pragma unroll
            for (int i = 0; i < acc.num_elements; i++) {
                int bi = (int)floorf((acc.x[i] - lo) * inv);
                bi = bi < 0 ? 0 : (bi > 15 ? 15 : bi);
                atomicAdd(&myh[bi], 1);
            }
        });

    __syncthreads();
    if (t < 16) {
        int s = 0;
#pragma unroll
        for (int w = 0; w < 8; w++) s += hsm[w][t];
        atomicAdd(&g_hist[t], s);
    }
}

// ---------------- final MLP head ----------------
__global__ void k_final(const float* __restrict__ fc1W, const float* __restrict__ fc1b,
                        const float* __restrict__ fc2W, const float* __restrict__ fc2b,
                        float* __restrict__ out) {
    __shared__ float h[16];
    const int b = threadIdx.x;
    if (b < 16) h[b] = (float)g_hist[b] * (1.0f / 8388608.0f);
    __syncthreads();

    float sc[16];
#pragma unroll
    for (int t = 0; t < 16; t++) sc[t] = g_scoresT[b * 16 + t];

    float p = fc2b[0];
#pragma unroll
    for (int j = 0; j < 16; j++) {
        float a = fc1b[j];
#pragma unroll
        for (int t = 0; t < 16; t++) a += sc[t] * fc1W[j * 32 + t];
#pragma unroll
        for (int k = 0; k < 16; k++) a += h[k] * fc1W[j * 32 + 16 + k];
        p += fmaxf(a, 0.f) * fc2W[j];
    }
    out[b] = 1.0f / (1.0f + expf(-p));
}

// ---------------- launch ----------------
extern "C" void kernel_launch(void* const* d_in, const int* in_sizes, int n_in,
                              void* d_out, int out_size) {
    const float* xq   = (const float*)d_in[0];
    const float* xc   = (const float*)d_in[1];
    const int*   eq   = (const int*)d_in[2];
    const int*   ec   = (const int*)d_in[3];
    const float* W1   = (const float*)d_in[4];
    const float* b1   = (const float*)d_in[5];
    const float* W2   = (const float*)d_in[6];
    const float* b2   = (const float*)d_in[7];
    const float* W3   = (const float*)d_in[8];
    const float* b3   = (const float*)d_in[9];
    const float* Watt = (const float*)d_in[10];
    const float* ntnW = (const float*)d_in[11];
    const float* ntnV = (const float*)d_in[12];
    const float* ntnb = (const float*)d_in[13];
    const float* fc1W = (const float*)d_in[14];
    const float* fc1b = (const float*)d_in[15];
    const float* fc2W = (const float*)d_in[16];
    const float* fc2b = (const float*)d_in[17];
    float* out = (float*)d_out;

    float *bufB;
    cudaGetSymbolAddress((void**)&bufB, g_bufB);
    __nv_bfloat16 *Xhi, *Xlo, *Yhi, *Ylo, *Whi, *Wlo;
    cudaGetSymbolAddress((void**)&Xhi, g_Xhi);
    cudaGetSymbolAddress((void**)&Xlo, g_Xlo);
    cudaGetSymbolAddress((void**)&Yhi, g_Yhi);
    cudaGetSymbolAddress((void**)&Ylo, g_Ylo);
    cudaGetSymbolAddress((void**)&Whi, g_Whi);
    cudaGetSymbolAddress((void**)&Wlo, g_Wlo);

    // smem: A(2*256*LDA*2) + W(2*K*LDB*2) + edges(E*8) + rowptr(258*4) + invdeg(256*4)
    constexpr int EDGE = E_ * 8 + 258 * 4 + 256 * 4;                 // 18,440
    constexpr int SMF1 = (2 * 256 * 136 + 2 * 128 * 136) * 2 + EDGE; // 227,336
    constexpr int SMF2 = (2 * 256 * 136 + 2 * 128 * 72)  * 2 + EDGE; // 194,568
    constexpr int SMF3 = (2 * 256 * 72  + 2 * 64 * 40)   * 2 + EDGE; // 102,408

    cudaFuncSetAttribute(k_fused<128, 128, 1>, cudaFuncAttributeMaxDynamicSharedMemorySize, SMF1);
    cudaFuncSetAttribute(k_fused<128, 64,  2>, cudaFuncAttributeMaxDynamicSharedMemorySize, SMF2);
    cudaFuncSetAttribute(k_fused<64,  32,  3>, cudaFuncAttributeMaxDynamicSharedMemorySize, SMF3);

    k_csr<<<GTOT, 256>>>(eq, ec);
    k_cvtW<<<104, 256>>>(W1, W2, W3);

    k_fused<128, 128, 1><<<GTOT, 512, SMF1>>>(xq, xc, nullptr, nullptr,
                                              Whi, Wlo, b1, Xhi, Xlo, nullptr);
    k_fused<128, 64, 2><<<GTOT, 512, SMF2>>>(nullptr, nullptr, Xhi, Xlo,
                                             Whi + 16384, Wlo + 16384, b2, Yhi, Ylo, nullptr);
    k_fused<64, 32, 3><<<GTOT, 512, SMF3>>>(nullptr, nullptr, Yhi, Ylo,
                                            Whi + 24576, Wlo + 24576, b3,
                                            nullptr, nullptr, bufB);

    k_pool<<<GTOT, 256>>>(bufB, Watt);
    k_ntn<<<B_, 512>>>(ntnW, ntnV, ntnb);

    k_pair_minmax<<<dim3(2, B_), 256>>>();
    k_pair_hist<<<dim3(2, B_), 256>>>();

    k_final<<<1, B_>>>(fc1W, fc1b, fc2W, fc2b, out);
}

// round 12
// speedup vs baseline: 1.4265x; 1.0968x over previous
#include <cuda_runtime.h>
#include <cuda_bf16.h>
#include <mma.h>
#include <cstdint>
#include <math.h>

using namespace nvcuda;

#define B_   128
#define N_   256
#define E_   2048
#define GTOT 256   // q graphs [0,128) + c graphs [128,256)

// ---------------- device scratch (static globals: no allocs) ----------------
__device__ __nv_bfloat16 g_Xhi[GTOT * N_ * 128];   // layer1 out hi (128-d)
__device__ __nv_bfloat16 g_Xlo[GTOT * N_ * 128];
__device__ __nv_bfloat16 g_Phi[GTOT * N_ * 32];    // final emb hi (for pair mm)
__device__ __nv_bfloat16 g_Plo[GTOT * N_ * 32];
__device__ __nv_bfloat16 g_Whi[26624];             // W1|W2|W3 bf16 hi
__device__ __nv_bfloat16 g_Wlo[26624];             // W1|W2|W3 bf16 lo
__device__ float2   g_edge[GTOT * E_];         // packed (coef, src-as-float-bits)
__device__ int      g_rowptr[GTOT * 257];
__device__ float    g_invdeg[GTOT * N_];
__device__ float    g_pool[GTOT * 32];
__device__ float    g_scoresT[B_ * 16];
__device__ unsigned g_minmax[2];
__device__ int      g_hist[16];

// monotone float<->uint mapping for atomicMin/Max over signed floats
__device__ __forceinline__ unsigned encf(float f) {
    unsigned u = __float_as_uint(f);
    return (u & 0x80000000u) ? ~u : (u | 0x80000000u);
}
__device__ __forceinline__ float decf(unsigned u) {
    return (u & 0x80000000u) ? __uint_as_float(u & 0x7fffffffu)
                             : __uint_as_float(~u);
}

// pack 4 floats -> (hi uint2, lo uint2) of bf16
__device__ __forceinline__ void split4(float4 v, uint2& hq, uint2& lq) {
    __nv_bfloat16 h0 = __float2bfloat16(v.x);
    __nv_bfloat16 h1 = __float2bfloat16(v.y);
    __nv_bfloat16 h2 = __float2bfloat16(v.z);
    __nv_bfloat16 h3 = __float2bfloat16(v.w);
    __nv_bfloat16 l0 = __float2bfloat16(v.x - __bfloat162float(h0));
    __nv_bfloat16 l1 = __float2bfloat16(v.y - __bfloat162float(h1));
    __nv_bfloat16 l2 = __float2bfloat16(v.z - __bfloat162float(h2));
    __nv_bfloat16 l3 = __float2bfloat16(v.w - __bfloat162float(h3));
    __nv_bfloat162 ph01(h0, h1), ph23(h2, h3), pl01(l0, l1), pl23(l2, l3);
    hq.x = *(unsigned*)&ph01; hq.y = *(unsigned*)&ph23;
    lq.x = *(unsigned*)&pl01; lq.y = *(unsigned*)&pl23;
}

// ---------------- weight conversion (one-shot) ----------------
__global__ void __launch_bounds__(256) k_cvtW(const float* __restrict__ W1,
                                              const float* __restrict__ W2,
                                              const float* __restrict__ W3) {
    int i = blockIdx.x * 256 + threadIdx.x;
    if (i >= 26624) return;
    float w = (i < 16384) ? W1[i] : (i < 24576 ? W2[i - 16384] : W3[i - 24576]);
    __nv_bfloat16 h = __float2bfloat16(w);
    g_Whi[i] = h;
    g_Wlo[i] = __float2bfloat16(w - __bfloat162float(h));
}

// ---------------- CSR build (per graph) + global init in block 0 ----------------
__global__ void __launch_bounds__(256) k_csr(const int* __restrict__ eq,
                                             const int* __restrict__ ec) {
    const int g = blockIdx.x;
    const int t = threadIdx.x;
    if (g == 0) {
        if (t == 0) { g_minmax[0] = 0xffffffffu; g_minmax[1] = 0u; }
        if (t < 16) g_hist[t] = 0;
    }
    const int* base = (g < B_) ? (eq + (size_t)g * 2 * E_)
                               : (ec + (size_t)(g - B_) * 2 * E_);
    const int* src = base;
    const int* dst = base + E_;

    __shared__ int   cnt[256];
    __shared__ int   scan[256];
    __shared__ int   off[256];
    __shared__ float dinv[256];

    cnt[t] = 0;
    __syncthreads();
    for (int e = t; e < E_; e += 256) atomicAdd(&cnt[dst[e]], 1);
    __syncthreads();

    float deg = (float)cnt[t] + 1.0f;
    dinv[t] = rsqrtf(deg);
    g_invdeg[g * N_ + t] = 1.0f / deg;

    int v = cnt[t];
    scan[t] = v;
    __syncthreads();
    for (int s = 1; s < 256; s <<= 1) {
        int add = (t >= s) ? scan[t - s] : 0;
        __syncthreads();
        scan[t] += add;
        __syncthreads();
    }
    int excl = scan[t] - v;
    off[t] = excl;
    g_rowptr[g * 257 + t] = excl;
    if (t == 0) g_rowptr[g * 257 + 256] = E_;
    __syncthreads();

    for (int e = t; e < E_; e += 256) {
        int d = dst[e];
        int s_ = src[e];
        int pos = atomicAdd(&off[d], 1);
        g_edge[g * E_ + pos] = make_float2(dinv[s_] * dinv[d], __int_as_float(s_));
    }
}

// ======================= layer 1: stage X -> wmma -> H smem -> agg -> Xhi/Xlo =======================
__global__ void __launch_bounds__(512) k_fused1(
    const float* __restrict__ in0, const float* __restrict__ in1,
    const __nv_bfloat16* __restrict__ Whi_, const __nv_bfloat16* __restrict__ Wlo_,
    const float* __restrict__ bias)
{
    constexpr int K = 128, FO = 128;
    constexpr int LDA = K + 8;
    constexpr int LDB = FO + 8;
    extern __shared__ __align__(16) char smc[];
    __nv_bfloat16* Ahi = (__nv_bfloat16*)smc;          // 256*LDA
    __nv_bfloat16* Alo = Ahi + 256 * LDA;
    __nv_bfloat16* Bhi = Alo + 256 * LDA;              // K*LDB
    __nv_bfloat16* Blo = Bhi + K * LDB;
    float2* esm = (float2*)(Blo + K * LDB);            // E_
    int*    rsm = (int*)(esm + E_);                    // 258
    float*  dsm = (float*)(rsm + 258);                 // 256

    const int g = blockIdx.x;
    const int t = threadIdx.x;
    const int wid = t >> 5;

    {
        const float* X = (g < B_) ? in0 + (size_t)g * N_ * K
                                  : in1 + (size_t)(g - B_) * N_ * K;
        const float4* X4 = (const float4*)X;
        constexpr int KQ = K / 4;
        for (int i = t; i < N_ * KQ; i += 512) {
            int r = i / KQ, c = i % KQ;
            uint2 hq, lq;
            split4(X4[i], hq, lq);
            ((uint2*)(Ahi + r * LDA))[c] = hq;
            ((uint2*)(Alo + r * LDA))[c] = lq;
        }
    }
    {
        constexpr int FQ = FO / 8;
        const uint4* GH = (const uint4*)Whi_;
        const uint4* GL = (const uint4*)Wlo_;
        for (int i = t; i < K * FQ; i += 512) {
            int r = i / FQ, c = i % FQ;
            ((uint4*)(Bhi + r * LDB))[c] = GH[i];
            ((uint4*)(Blo + r * LDB))[c] = GL[i];
        }
    }
    for (int i = t; i < E_; i += 512) esm[i] = g_edge[(size_t)g * E_ + i];
    for (int i = t; i < 257; i += 512) rsm[i] = g_rowptr[g * 257 + i];
    for (int i = t; i < 256; i += 512) dsm[i] = g_invdeg[g * N_ + i];
    __syncthreads();

    constexpr int NT = FO / 16;
    wmma::fragment<wmma::accumulator, 16, 16, 16, float> C[NT];
#pragma unroll
    for (int n = 0; n < NT; n++) wmma::fill_fragment(C[n], 0.0f);

    const __nv_bfloat16* Ah = Ahi + (size_t)(wid * 16) * LDA;
    const __nv_bfloat16* Al = Alo + (size_t)(wid * 16) * LDA;
#pragma unroll
    for (int k0 = 0; k0 < K; k0 += 16) {
        wmma::fragment<wmma::matrix_a, 16, 16, 16, __nv_bfloat16, wmma::row_major> ah, al;
        wmma::load_matrix_sync(ah, Ah + k0, LDA);
        wmma::load_matrix_sync(al, Al + k0, LDA);
#pragma unroll
        for (int n = 0; n < NT; n++) {
            wmma::fragment<wmma::matrix_b, 16, 16, 16, __nv_bfloat16, wmma::row_major> bh, bl;
            wmma::load_matrix_sync(bh, Bhi + (size_t)k0 * LDB + n * 16, LDB);
            wmma::load_matrix_sync(bl, Blo + (size_t)k0 * LDB + n * 16, LDB);
            wmma::mma_sync(C[n], ah, bh, C[n]);
            wmma::mma_sync(C[n], ah, bl, C[n]);
            wmma::mma_sync(C[n], al, bh, C[n]);
        }
    }
    __syncthreads();

    float* Hs = (float*)smc;
#pragma unroll
    for (int n = 0; n < NT; n++)
        wmma::store_matrix_sync(Hs + (size_t)(wid * 16) * FO + n * 16, C[n],
                                FO, wmma::mem_row_major);
    __syncthreads();

    constexpr int QPN = FO / 4;
    constexpr int NPB = 512 / QPN;
    const int fq = t % QPN;
    const int n0 = t / QPN;
    const float4 bf = ((const float4*)bias)[fq];
    const float4* h4 = (const float4*)Hs;
    uint2* OHI = (uint2*)g_Xhi + (size_t)g * N_ * QPN;
    uint2* OLO = (uint2*)g_Xlo + (size_t)g * N_ * QPN;

    for (int n = n0; n < N_; n += NPB) {
        const int e0 = rsm[n], e1 = rsm[n + 1];
        float4 a0 = make_float4(0.f, 0.f, 0.f, 0.f);
        float4 a1 = make_float4(0.f, 0.f, 0.f, 0.f);
        int e = e0;
        for (; e + 1 < e1; e += 2) {
            float2 ed0 = esm[e];
            float2 ed1 = esm[e + 1];
            float4 h0 = h4[__float_as_int(ed0.y) * QPN + fq];
            float4 h1 = h4[__float_as_int(ed1.y) * QPN + fq];
            a0.x += h0.x * ed0.x; a0.y += h0.y * ed0.x;
            a0.z += h0.z * ed0.x; a0.w += h0.w * ed0.x;
            a1.x += h1.x * ed1.x; a1.y += h1.y * ed1.x;
            a1.z += h1.z * ed1.x; a1.w += h1.w * ed1.x;
        }
        if (e < e1) {
            float2 ed0 = esm[e];
            float4 h0 = h4[__float_as_int(ed0.y) * QPN + fq];
            a0.x += h0.x * ed0.x; a0.y += h0.y * ed0.x;
            a0.z += h0.z * ed0.x; a0.w += h0.w * ed0.x;
        }
        const float id = dsm[n];
        float4 hs = h4[n * QPN + fq];
        float4 v;
        v.x = fmaxf(a0.x + a1.x + hs.x * id + bf.x, 0.f);
        v.y = fmaxf(a0.y + a1.y + hs.y * id + bf.y, 0.f);
        v.z = fmaxf(a0.z + a1.z + hs.z * id + bf.z, 0.f);
        v.w = fmaxf(a0.w + a1.w + hs.w * id + bf.w, 0.f);
        uint2 hq, lq;
        split4(v, hq, lq);
        OHI[n * QPN + fq] = hq;
        OLO[n * QPN + fq] = lq;
    }
}

// ======================= layers 2+3 + attention pooling, fully smem-resident =======================
// smem map (bytes):
//   [0, 139264)        A-region: A2 hi/lo (LDA2=136); later H2 fp32 [0,64K), A3 hi/lo [64K,137.7K),
//                      H3 fp32 [0,32K), emb fp32 [32K,64K)
//   [139264, 186368)   W-region: W2hi 18432 | W2lo 18432 | W3hi 5120 | W3lo 5120
//   [186368, 202752)   edges (E_ float2)
//   [202752, 203784)   rowptr (258 int)
//   [203784, 204808)   invdeg (256 f)
//   [204808, 206344)   pool scratch: colsum 32f | ctx 32f | score 256f | pad
__global__ void __launch_bounds__(512) k_fused23(
    const __nv_bfloat16* __restrict__ W2hi_, const __nv_bfloat16* __restrict__ W2lo_,
    const __nv_bfloat16* __restrict__ W3hi_, const __nv_bfloat16* __restrict__ W3lo_,
    const float* __restrict__ b2, const float* __restrict__ b3,
    const float* __restrict__ Watt)
{
    constexpr int LDA2 = 136, LDB2 = 72, LDA3 = 72, LDB3 = 40;
    extern __shared__ __align__(16) char smc[];
    __nv_bfloat16* A2hi = (__nv_bfloat16*)smc;
    __nv_bfloat16* A2lo = A2hi + 256 * LDA2;
    __nv_bfloat16* W2hi = (__nv_bfloat16*)(smc + 139264);
    __nv_bfloat16* W2lo = W2hi + 128 * LDB2;
    __nv_bfloat16* W3hi = W2lo + 128 * LDB2;
    __nv_bfloat16* W3lo = W3hi + 64 * LDB3;
    float2* esm = (float2*)(smc + 186368);
    int*    rsm = (int*)(smc + 202752);
    float*  dsm = (float*)(smc + 203784);
    float*  colsum = (float*)(smc + 204808);
    float*  ctx    = colsum + 32;
    float*  score  = ctx + 32;

    float* H2  = (float*)smc;                          // [0, 64K)
    __nv_bfloat16* A3hi = (__nv_bfloat16*)(smc + 65536);
    __nv_bfloat16* A3lo = A3hi + 256 * LDA3;
    float* H3  = (float*)smc;                          // [0, 32K)
    float* Es  = (float*)(smc + 32768);                // emb fp32 [32K, 64K)

    const int g = blockIdx.x;
    const int t = threadIdx.x;
    const int wid = t >> 5;

    // ---- stage A2 (from layer1 output), W2, W3, edges ----
    {
        const uint4* GH = (const uint4*)(g_Xhi + (size_t)g * N_ * 128);
        const uint4* GL = (const uint4*)(g_Xlo + (size_t)g * N_ * 128);
        for (int i = t; i < N_ * 16; i += 512) {
            int r = i / 16, c = i % 16;
            ((uint4*)(A2hi + r * LDA2))[c] = GH[i];
            ((uint4*)(A2lo + r * LDA2))[c] = GL[i];
        }
    }
    {
        const uint4* GH = (const uint4*)W2hi_;
        const uint4* GL = (const uint4*)W2lo_;
        for (int i = t; i < 128 * 8; i += 512) {
            int r = i / 8, c = i % 8;
            ((uint4*)(W2hi + r * LDB2))[c] = GH[i];
            ((uint4*)(W2lo + r * LDB2))[c] = GL[i];
        }
        const uint4* GH3 = (const uint4*)W3hi_;
        const uint4* GL3 = (const uint4*)W3lo_;
        for (int i = t; i < 64 * 4; i += 512) {
            int r = i / 4, c = i % 4;
            ((uint4*)(W3hi + r * LDB3))[c] = GH3[i];
            ((uint4*)(W3lo + r * LDB3))[c] = GL3[i];
        }
    }
    for (int i = t; i < E_; i += 512) esm[i] = g_edge[(size_t)g * E_ + i];
    for (int i = t; i < 257; i += 512) rsm[i] = g_rowptr[g * 257 + i];
    for (int i = t; i < 256; i += 512) dsm[i] = g_invdeg[g * N_ + i];
    __syncthreads();

    // ======== layer 2 GEMM: 16 warps x 16 rows, FO=64 (NT=4) ========
    {
        wmma::fragment<wmma::accumulator, 16, 16, 16, float> C[4];
#pragma unroll
        for (int n = 0; n < 4; n++) wmma::fill_fragment(C[n], 0.0f);
        const __nv_bfloat16* Ah = A2hi + (size_t)(wid * 16) * LDA2;
        const __nv_bfloat16* Al = A2lo + (size_t)(wid * 16) * LDA2;
#pragma unroll
        for (int k0 = 0; k0 < 128; k0 += 16) {
            wmma::fragment<wmma::matrix_a, 16, 16, 16, __nv_bfloat16, wmma::row_major> ah, al;
            wmma::load_matrix_sync(ah, Ah + k0, LDA2);
            wmma::load_matrix_sync(al, Al + k0, LDA2);
#pragma unroll
            for (int n = 0; n < 4; n++) {
                wmma::fragment<wmma::matrix_b, 16, 16, 16, __nv_bfloat16, wmma::row_major> bh, bl;
                wmma::load_matrix_sync(bh, W2hi + (size_t)k0 * LDB2 + n * 16, LDB2);
                wmma::load_matrix_sync(bl, W2lo + (size_t)k0 * LDB2 + n * 16, LDB2);
                wmma::mma_sync(C[n], ah, bh, C[n]);
                wmma::mma_sync(C[n], ah, bl, C[n]);
                wmma::mma_sync(C[n], al, bh, C[n]);
            }
        }
        __syncthreads();   // A2 reads done -> overlay H2
#pragma unroll
        for (int n = 0; n < 4; n++)
            wmma::store_matrix_sync(H2 + (size_t)(wid * 16) * 64 + n * 16, C[n],
                                    64, wmma::mem_row_major);
        __syncthreads();
    }

    // ======== layer 2 aggregate: H2 -> A3 (bf16 hi/lo, relu) ========
    {
        constexpr int QPN = 16;   // 64/4
        constexpr int NPB = 32;
        const int fq = t % QPN;
        const int n0 = t / QPN;
        const float4 bf = ((const float4*)b2)[fq];
        const float4* h4 = (const float4*)H2;
        for (int n = n0; n < N_; n += NPB) {
            const int e0 = rsm[n], e1 = rsm[n + 1];
            float4 a0 = make_float4(0.f, 0.f, 0.f, 0.f);
            float4 a1 = make_float4(0.f, 0.f, 0.f, 0.f);
            int e = e0;
            for (; e + 1 < e1; e += 2) {
                float2 ed0 = esm[e];
                float2 ed1 = esm[e + 1];
                float4 h0 = h4[__float_as_int(ed0.y) * QPN + fq];
                float4 h1 = h4[__float_as_int(ed1.y) * QPN + fq];
                a0.x += h0.x * ed0.x; a0.y += h0.y * ed0.x;
                a0.z += h0.z * ed0.x; a0.w += h0.w * ed0.x;
                a1.x += h1.x * ed1.x; a1.y += h1.y * ed1.x;
                a1.z += h1.z * ed1.x; a1.w += h1.w * ed1.x;
            }
            if (e < e1) {
                float2 ed0 = esm[e];
                float4 h0 = h4[__float_as_int(ed0.y) * QPN + fq];
                a0.x += h0.x * ed0.x; a0.y += h0.y * ed0.x;
                a0.z += h0.z * ed0.x; a0.w += h0.w * ed0.x;
            }
            const float id = dsm[n];
            float4 hs = h4[n * QPN + fq];
            float4 v;
            v.x = fmaxf(a0.x + a1.x + hs.x * id + bf.x, 0.f);
            v.y = fmaxf(a0.y + a1.y + hs.y * id + bf.y, 0.f);
            v.z = fmaxf(a0.z + a1.z + hs.z * id + bf.z, 0.f);
            v.w = fmaxf(a0.w + a1.w + hs.w * id + bf.w, 0.f);
            uint2 hq, lq;
            split4(v, hq, lq);
            ((uint2*)(A3hi + n * LDA3))[fq] = hq;
            ((uint2*)(A3lo + n * LDA3))[fq] = lq;
        }
        __syncthreads();
    }

    // ======== layer 3 GEMM: K=64, FO=32 (NT=2) ========
    {
        wmma::fragment<wmma::accumulator, 16, 16, 16, float> C[2];
#pragma unroll
        for (int n = 0; n < 2; n++) wmma::fill_fragment(C[n], 0.0f);
        const __nv_bfloat16* Ah = A3hi + (size_t)(wid * 16) * LDA3;
        const __nv_bfloat16* Al = A3lo + (size_t)(wid * 16) * LDA3;
#pragma unroll
        for (int k0 = 0; k0 < 64; k0 += 16) {
            wmma::fragment<wmma::matrix_a, 16, 16, 16, __nv_bfloat16, wmma::row_major> ah, al;
            wmma::load_matrix_sync(ah, Ah + k0, LDA3);
            wmma::load_matrix_sync(al, Al + k0, LDA3);
#pragma unroll
            for (int n = 0; n < 2; n++) {
                wmma::fragment<wmma::matrix_b, 16, 16, 16, __nv_bfloat16, wmma::row_major> bh, bl;
                wmma::load_matrix_sync(bh, W3hi + (size_t)k0 * LDB3 + n * 16, LDB3);
                wmma::load_matrix_sync(bl, W3lo + (size_t)k0 * LDB3 + n * 16, LDB3);
                wmma::mma_sync(C[n], ah, bh, C[n]);
                wmma::mma_sync(C[n], ah, bl, C[n]);
                wmma::mma_sync(C[n], al, bh, C[n]);
            }
        }
        __syncthreads();   // H2 region dead (agg2 done), A3 reads done -> H3 at [0,32K)
#pragma unroll
        for (int n = 0; n < 2; n++)
            wmma::store_matrix_sync(H3 + (size_t)(wid * 16) * 32 + n * 16, C[n],
                                    32, wmma::mem_row_major);
        __syncthreads();
    }

    // ======== layer 3 aggregate: H3 -> emb fp32 (smem) + Phi/Plo (global) ========
    {
        constexpr int QPN = 8;    // 32/4
        constexpr int NPB = 64;
        const int fq = t % QPN;
        const int n0 = t / QPN;
        const float4 bf = ((const float4*)b3)[fq];
        const float4* h4 = (const float4*)H3;
        uint2* PHI = (uint2*)g_Phi + (size_t)g * N_ * QPN;
        uint2* PLO = (uint2*)g_Plo + (size_t)g * N_ * QPN;
        for (int n = n0; n < N_; n += NPB) {
            const int e0 = rsm[n], e1 = rsm[n + 1];
            float4 a0 = make_float4(0.f, 0.f, 0.f, 0.f);
            float4 a1 = make_float4(0.f, 0.f, 0.f, 0.f);
            int e = e0;
            for (; e + 1 < e1; e += 2) {
                float2 ed0 = esm[e];
                float2 ed1 = esm[e + 1];
                float4 h0 = h4[__float_as_int(ed0.y) * QPN + fq];
                float4 h1 = h4[__float_as_int(ed1.y) * QPN + fq];
                a0.x += h0.x * ed0.x; a0.y += h0.y * ed0.x;
                a0.z += h0.z * ed0.x; a0.w += h0.w * ed0.x;
                a1.x += h1.x * ed1.x; a1.y += h1.y * ed1.x;
                a1.z += h1.z * ed1.x; a1.w += h1.w * ed1.x;
            }
            if (e < e1) {
                float2 ed0 = esm[e];
                float4 h0 = h4[__float_as_int(ed0.y) * QPN + fq];
                a0.x += h0.x * ed0.x; a0.y += h0.y * ed0.x;
                a0.z += h0.z * ed0.x; a0.w += h0.w * ed0.x;
            }
            const float id = dsm[n];
            float4 hs = h4[n * QPN + fq];
            float4 v;
            v.x = a0.x + a1.x + hs.x * id + bf.x;
            v.y = a0.y + a1.y + hs.y * id + bf.y;
            v.z = a0.z + a1.z + hs.z * id + bf.z;
            v.w = a0.w + a1.w + hs.w * id + bf.w;
            ((float4*)Es)[n * QPN + fq] = v;
            uint2 hq, lq;
            split4(v, hq, lq);
            PHI[n * QPN + fq] = hq;
            PLO[n * QPN + fq] = lq;
        }
        __syncthreads();
    }

    // ======== attention pooling (in-smem, staggered conflict-free) ========
    if (t < 32) {
        float s = 0.f;
        for (int n = 0; n < N_; n++) s += Es[n * 32 + t];
        colsum[t] = s;
    }
    __syncthreads();
    if (t < 32) {
        float a = 0.f;
        for (int i = 0; i < 32; i++) a += colsum[i] * Watt[t * 32 + i];
        ctx[t] = tanhf(a * (1.0f / 256.0f));
    }
    __syncthreads();
    if (t < 256) {
        const int lane = t & 31;
        float d = 0.f;
#pragma unroll
        for (int j = 0; j < 32; j++) {
            int i = (lane + j) & 31;
            d += Es[t * 32 + i] * ctx[i];
        }
        score[t] = 1.0f / (1.0f + expf(-d));
    }
    __syncthreads();
    if (t < 32) {
        float s = 0.f;
        for (int n = 0; n < N_; n++) s += Es[n * 32 + t] * score[n];
        g_pool[g * 32 + t] = s;
    }
}

// ---------------- NTN ----------------
__global__ void __launch_bounds__(512) k_ntn(const float* __restrict__ ntnW,
                                             const float* __restrict__ ntnV,
                                             const float* __restrict__ ntnb) {
    const int b = blockIdx.x;
    __shared__ float e1[32], e2[32];
    const int t = threadIdx.x;
    if (t < 32)      e1[t]      = g_pool[b * 32 + t];
    else if (t < 64) e2[t - 32] = g_pool[(B_ + b) * 32 + (t - 32)];
    __syncthreads();

    const int w = t >> 5, lane = t & 31;
    const float* Wt = ntnW + w * 1024;
    float a = 0.f;
#pragma unroll 8
    for (int j = 0; j < 32; j++) a += Wt[lane * 32 + j] * e2[j];
    float partial = e1[lane] * a
                  + e1[lane] * ntnV[w * 64 + lane]
                  + e2[lane] * ntnV[w * 64 + 32 + lane];
#pragma unroll
    for (int o = 16; o; o >>= 1)
        partial += __shfl_xor_sync(0xffffffffu, partial, o);
    if (lane == 0)
        g_scoresT[b * 16 + w] = fmaxf(partial + ntnb[w], 0.f);
}

// ============ pair matrix: shared staging + split-bf16 wmma tile compute ============
template<typename F>
__device__ __forceinline__ void pair_tiles(int half, int b, int t, F&& consume) {
    constexpr int LD = 40;
    __shared__ __align__(16) __nv_bfloat16 Qh[128 * LD];
    __shared__ __align__(16) __nv_bfloat16 Ql[128 * LD];
    __shared__ __align__(16) __nv_bfloat16 Ch[256 * LD];
    __shared__ __align__(16) __nv_bfloat16 Cl[256 * LD];

    const int wid = t >> 5;

    {
        const uint4* QH = (const uint4*)(g_Phi + ((size_t)b * N_ + half * 128) * 32);
        const uint4* QL = (const uint4*)(g_Plo + ((size_t)b * N_ + half * 128) * 32);
        for (int i = t; i < 128 * 4; i += 256) {
            int r = i / 4, c = i % 4;
            ((uint4*)(Qh + r * LD))[c] = QH[i];
            ((uint4*)(Ql + r * LD))[c] = QL[i];
        }
        const uint4* CH = (const uint4*)(g_Phi + (size_t)(B_ + b) * N_ * 32);
        const uint4* CL = (const uint4*)(g_Plo + (size_t)(B_ + b) * N_ * 32);
        for (int i = t; i < 256 * 4; i += 256) {
            int r = i / 4, c = i % 4;
            ((uint4*)(Ch + r * LD))[c] = CH[i];
            ((uint4*)(Cl + r * LD))[c] = CL[i];
        }
    }
    __syncthreads();

    wmma::fragment<wmma::matrix_a, 16, 16, 16, __nv_bfloat16, wmma::row_major> ah[2], al[2];
#pragma unroll
    for (int kt = 0; kt < 2; kt++) {
        wmma::load_matrix_sync(ah[kt], Qh + (size_t)(wid * 16) * LD + kt * 16, LD);
        wmma::load_matrix_sync(al[kt], Ql + (size_t)(wid * 16) * LD + kt * 16, LD);
    }

#pragma unroll
    for (int ct = 0; ct < 16; ct++) {
        wmma::fragment<wmma::accumulator, 16, 16, 16, float> acc;
        wmma::fill_fragment(acc, 0.0f);
#pragma unroll
        for (int kt = 0; kt < 2; kt++) {
            wmma::fragment<wmma::matrix_b, 16, 16, 16, __nv_bfloat16, wmma::col_major> bh, bl;
            wmma::load_matrix_sync(bh, Ch + (size_t)(ct * 16) * LD + kt * 16, LD);
            wmma::load_matrix_sync(bl, Cl + (size_t)(ct * 16) * LD + kt * 16, LD);
            wmma::mma_sync(acc, ah[kt], bh, acc);
            wmma::mma_sync(acc, ah[kt], bl, acc);
            wmma::mma_sync(acc, al[kt], bh, acc);
        }
        consume(acc);
    }
}

// ---- pass 1: global min/max only ----
__global__ void __launch_bounds__(256) k_pair_minmax() {
    __shared__ float wmn[8], wmx[8];
    const int half = blockIdx.x, b = blockIdx.y;
    const int t = threadIdx.x, wid = t >> 5, lane = t & 31;

    float vmin = 3.402823466e38f, vmax = -3.402823466e38f;
    pair_tiles(half, b, t,
        [&](wmma::fragment<wmma::accumulator, 16, 16, 16, float>& acc) {
#pragma unroll
            for (int i = 0; i < acc.num_elements; i++) {
                vmin = fminf(vmin, acc.x[i]);
                vmax = fmaxf(vmax, acc.x[i]);
            }
        });

#pragma unroll
    for (int o = 16; o; o >>= 1) {
        vmin = fminf(vmin, __shfl_xor_sync(0xffffffffu, vmin, o));
        vmax = fmaxf(vmax, __shfl_xor_sync(0xffffffffu, vmax, o));
    }
    if (lane == 0) { wmn[wid] = vmin; wmx[wid] = vmax; }
    __syncthreads();
    if (t == 0) {
        float m = wmn[0], M = wmx[0];
        for (int i = 1; i < 8; i++) { m = fminf(m, wmn[i]); M = fmaxf(M, wmx[i]); }
        atomicMin(&g_minmax[0], encf(m));
        atomicMax(&g_minmax[1], encf(M));
    }
}

// ---- pass 2: recompute identical tiles, histogram directly ----
__global__ void __launch_bounds__(256) k_pair_hist() {
    __shared__ int hsm[8][16];
    const int half = blockIdx.x, b = blockIdx.y;
    const int t = threadIdx.x, wid = t >> 5;

    if ((t & 31) < 16) hsm[wid][t & 15] = 0;
    __syncthreads();

    const float lo = decf(g_minmax[0]);
    const float inv = 16.0f / (decf(g_minmax[1]) - lo);
    int* myh = hsm[wid];

    pair_tiles(half, b, t,
        [&](wmma::fragment<wmma::accumulator, 16, 16, 16, float>& acc) {
#pragma unroll
            for (int i = 0; i < acc.num_elements; i++) {
                int bi = (int)floorf((acc.x[i] - lo) * inv);
                bi = bi < 0 ? 0 : (bi > 15 ? 15 : bi);
                atomicAdd(&myh[bi], 1);
            }
        });

    __syncthreads();
    if (t < 16) {
        int s = 0;
#pragma unroll
        for (int w = 0; w < 8; w++) s += hsm[w][t];
        atomicAdd(&g_hist[t], s);
    }
}

// ---------------- final MLP head ----------------
__global__ void k_final(const float* __restrict__ fc1W, const float* __restrict__ fc1b,
                        const float* __restrict__ fc2W, const float* __restrict__ fc2b,
                        float* __restrict__ out) {
    __shared__ float h[16];
    const int b = threadIdx.x;
    if (b < 16) h[b] = (float)g_hist[b] * (1.0f / 8388608.0f);
    __syncthreads();

    float sc[16];
#pragma unroll
    for (int t = 0; t < 16; t++) sc[t] = g_scoresT[b * 16 + t];

    float p = fc2b[0];
#pragma unroll
    for (int j = 0; j < 16; j++) {
        float a = fc1b[j];
#pragma unroll
        for (int t = 0; t < 16; t++) a += sc[t] * fc1W[j * 32 + t];
#pragma unroll
        for (int k = 0; k < 16; k++) a += h[k] * fc1W[j * 32 + 16 + k];
        p += fmaxf(a, 0.f) * fc2W[j];
    }
    out[b] = 1.0f / (1.0f + expf(-p));
}

// ---------------- launch ----------------
extern "C" void kernel_launch(void* const* d_in, const int* in_sizes, int n_in,
                              void* d_out, int out_size) {
    const float* xq   = (const float*)d_in[0];
    const float* xc   = (const float*)d_in[1];
    const int*   eq   = (const int*)d_in[2];
    const int*   ec   = (const int*)d_in[3];
    const float* W1   = (const float*)d_in[4];
    const float* b1   = (const float*)d_in[5];
    const float* W2   = (const float*)d_in[6];
    const float* b2   = (const float*)d_in[7];
    const float* W3   = (const float*)d_in[8];
    const float* b3   = (const float*)d_in[9];
    const float* Watt = (const float*)d_in[10];
    const float* ntnW = (const float*)d_in[11];
    const float* ntnV = (const float*)d_in[12];
    const float* ntnb = (const float*)d_in[13];
    const float* fc1W = (const float*)d_in[14];
    const float* fc1b = (const float*)d_in[15];
    const float* fc2W = (const float*)d_in[16];
    const float* fc2b = (const float*)d_in[17];
    float* out = (float*)d_out;

    __nv_bfloat16 *Whi, *Wlo;
    cudaGetSymbolAddress((void**)&Whi, g_Whi);
    cudaGetSymbolAddress((void**)&Wlo, g_Wlo);

    constexpr int EDGE = E_ * 8 + 258 * 4 + 256 * 4;                 // 18,440
    constexpr int SMF1  = (2 * 256 * 136 + 2 * 128 * 136) * 2 + EDGE; // 227,336
    constexpr int SMF23 = 139264 + 47104 + EDGE + 1536;               // 206,344

    cudaFuncSetAttribute(k_fused1,  cudaFuncAttributeMaxDynamicSharedMemorySize, SMF1);
    cudaFuncSetAttribute(k_fused23, cudaFuncAttributeMaxDynamicSharedMemorySize, SMF23);

    k_csr<<<GTOT, 256>>>(eq, ec);
    k_cvtW<<<104, 256>>>(W1, W2, W3);

    k_fused1<<<GTOT, 512, SMF1>>>(xq, xc, Whi, Wlo, b1);
    k_fused23<<<GTOT, 512, SMF23>>>(Whi + 16384, Wlo + 16384,
                                    Whi + 24576, Wlo + 24576, b2, b3, Watt);

    k_ntn<<<B_, 512>>>(ntnW, ntnV, ntnb);

    k_pair_minmax<<<dim3(2, B_), 256>>>();
    k_pair_hist<<<dim3(2, B_), 256>>>();

    k_final<<<1, B_>>>(fc1W, fc1b, fc2W, fc2b, out);
}